// round 2
// baseline (speedup 1.0000x reference)
#include <cuda_runtime.h>
#include <cstddef>

#define N_NODES 200000
#define C 128
#define S 6
#define EP 100000
#define EL 25000

typedef unsigned long long u64;
typedef unsigned int u32;

// ---- static device scratch (no allocations allowed) ----
__device__ float g_F[(size_t)N_NODES * C];
__device__ float g_G[(size_t)N_NODES * C];
__device__ float g_T[(size_t)N_NODES * C];
__device__ float g_X[(size_t)N_NODES * C];
__device__ float g_M[(size_t)N_NODES * (C + 4)];

// ---- packed f32x2 helpers ----
__device__ __forceinline__ u64 dup2f(float x) {
    u64 r; u32 xi = __float_as_uint(x);
    asm("mov.b64 %0, {%1, %1};" : "=l"(r) : "r"(xi));
    return r;
}
__device__ __forceinline__ void ffma2(u64& d, u64 a, u64 b) {
    asm("fma.rn.f32x2 %0, %1, %2, %0;" : "+l"(d) : "l"(a), "l"(b));
}
__device__ __forceinline__ void unpack2f(u64 v, float& lo, float& hi) {
    u32 l, h;
    asm("mov.b64 {%0, %1}, %2;" : "=r"(l), "=r"(h) : "l"(v));
    lo = __uint_as_float(l); hi = __uint_as_float(h);
}
__device__ __forceinline__ void red4(float* p, float a, float b, float c, float d) {
    asm volatile("red.global.add.v4.f32 [%0], {%1,%2,%3,%4};"
                 :: "l"(p), "f"(a), "f"(b), "f"(c), "f"(d) : "memory");
}

// ---- fused GEMM: out[m][:] (+)= A[m or src[m]][:K] @ W[K][128] ----
template<int K, int GATHER, int DOGN, int DOADD, int DORELU, int DORED>
__global__ __launch_bounds__(256, 2) void gemm_k(
    const float* __restrict__ A,
    const float* __restrict__ Wbase, long long wstride,
    float* __restrict__ out,
    const float* __restrict__ gng, const float* __restrict__ gnb,
    const float* __restrict__ addb,
    const int* __restrict__ dst_base, const int* __restrict__ src_base,
    long long istride, int nrows)
{
    extern __shared__ float sm[];
    float* As = sm;            // [K][64]
    float* Ws = sm + K * 64;   // [K][128]
    __shared__ int s_dst[64];
    __shared__ int s_src[64];

    const int tid  = threadIdx.x;
    const int row0 = blockIdx.x * 64;
    const float* Wp = Wbase + (long long)blockIdx.y * wstride;

    if (GATHER) {
        if (tid < 64) {
            int e = row0 + tid;
            const int* dp = dst_base + (long long)blockIdx.y * istride;
            const int* sp = src_base + (long long)blockIdx.y * istride;
            s_dst[tid] = (e < nrows) ? dp[e] : -1;
            s_src[tid] = (e < nrows) ? sp[e] : 0;
        }
        __syncthreads();
    }

    for (int v = tid; v < K * 32; v += 256)
        *(float4*)(Ws + (size_t)v * 4) = *(const float4*)(Wp + (size_t)v * 4);

    for (int v = tid; v < 64 * (K / 4); v += 256) {
        int m  = v & 63;
        int kq = v >> 6;
        float4 a = make_float4(0.f, 0.f, 0.f, 0.f);
        if (GATHER) {
            a = *(const float4*)(A + (size_t)s_src[m] * K + kq * 4);
        } else {
            int row = row0 + m;
            if (row < nrows) a = *(const float4*)(A + (size_t)row * K + kq * 4);
        }
        As[(4 * kq + 0) * 64 + m] = a.x;
        As[(4 * kq + 1) * 64 + m] = a.y;
        As[(4 * kq + 2) * 64 + m] = a.z;
        As[(4 * kq + 3) * 64 + m] = a.w;
    }
    __syncthreads();

    const int tc = tid & 31;   // col group: cols tc*4..tc*4+3
    const int tr = tid >> 5;   // row group: rows tr*8..tr*8+7 (warp == fixed tr)

    u64 acc[8][2];
    #pragma unroll
    for (int i = 0; i < 8; i++) { acc[i][0] = 0ULL; acc[i][1] = 0ULL; }

    const float* ap = As + tr * 8;
    const float* bp = Ws + tc * 4;

    #pragma unroll 4
    for (int k = 0; k < K; k++) {
        float4 a0 = *(const float4*)(ap + (size_t)k * 64);
        float4 a1 = *(const float4*)(ap + (size_t)k * 64 + 4);
        ulonglong2 b = *(const ulonglong2*)(bp + (size_t)k * 128);
        u64 av;
        av = dup2f(a0.x); ffma2(acc[0][0], av, b.x); ffma2(acc[0][1], av, b.y);
        av = dup2f(a0.y); ffma2(acc[1][0], av, b.x); ffma2(acc[1][1], av, b.y);
        av = dup2f(a0.z); ffma2(acc[2][0], av, b.x); ffma2(acc[2][1], av, b.y);
        av = dup2f(a0.w); ffma2(acc[3][0], av, b.x); ffma2(acc[3][1], av, b.y);
        av = dup2f(a1.x); ffma2(acc[4][0], av, b.x); ffma2(acc[4][1], av, b.y);
        av = dup2f(a1.y); ffma2(acc[5][0], av, b.x); ffma2(acc[5][1], av, b.y);
        av = dup2f(a1.z); ffma2(acc[6][0], av, b.x); ffma2(acc[6][1], av, b.y);
        av = dup2f(a1.w); ffma2(acc[7][0], av, b.x); ffma2(acc[7][1], av, b.y);
    }

    float c[8][4];
    #pragma unroll
    for (int mi = 0; mi < 8; mi++) {
        unpack2f(acc[mi][0], c[mi][0], c[mi][1]);
        unpack2f(acc[mi][1], c[mi][2], c[mi][3]);
    }

    if (DORED) {
        #pragma unroll
        for (int mi = 0; mi < 8; mi++) {
            int d = s_dst[tr * 8 + mi];
            if (d >= 0)
                red4(out + (size_t)d * C + tc * 4, c[mi][0], c[mi][1], c[mi][2], c[mi][3]);
        }
        return;
    }

    if (DOGN) {
        float gg[4], bb[4];
        *(float4*)gg = *(const float4*)(gng + tc * 4);
        *(float4*)bb = *(const float4*)(gnb + tc * 4);
        #pragma unroll
        for (int mi = 0; mi < 8; mi++) {
            float s1 = c[mi][0] + c[mi][1] + c[mi][2] + c[mi][3];
            float s2 = c[mi][0]*c[mi][0] + c[mi][1]*c[mi][1]
                     + c[mi][2]*c[mi][2] + c[mi][3]*c[mi][3];
            #pragma unroll
            for (int o = 16; o >= 1; o >>= 1) {
                s1 += __shfl_xor_sync(0xffffffffu, s1, o);
                s2 += __shfl_xor_sync(0xffffffffu, s2, o);
            }
            float mu  = s1 * (1.f / 128.f);
            float var = s2 * (1.f / 128.f) - mu * mu;
            float sc  = rsqrtf(var + 1e-5f);
            #pragma unroll
            for (int j = 0; j < 4; j++)
                c[mi][j] = (c[mi][j] - mu) * sc * gg[j] + bb[j];
        }
    }

    #pragma unroll
    for (int mi = 0; mi < 8; mi++) {
        int row = row0 + tr * 8 + mi;
        if (row < nrows) {
            if (DOADD) {
                float4 r = *(const float4*)(addb + (size_t)row * C + tc * 4);
                c[mi][0] += r.x; c[mi][1] += r.y; c[mi][2] += r.z; c[mi][3] += r.w;
            }
            if (DORELU) {
                #pragma unroll
                for (int j = 0; j < 4; j++) c[mi][j] = fmaxf(c[mi][j], 0.f);
            }
            *(float4*)(out + (size_t)row * C + tc * 4) =
                make_float4(c[mi][0], c[mi][1], c[mi][2], c[mi][3]);
        }
    }
}

// ---- elementwise kernels ----
__global__ void ew_in(const float* __restrict__ ctrs, const float* __restrict__ feats,
                      const float* __restrict__ w_in1, const float* __restrict__ b_in1,
                      const float* __restrict__ w_seg1, const float* __restrict__ b_seg1,
                      float* __restrict__ H1, float* __restrict__ H2)
{
    int i = blockIdx.x * 256 + threadIdx.x;
    if (i >= N_NODES * C) return;
    int n = i >> 7, cc = i & 127;
    float x0 = ctrs[2 * n], x1 = ctrs[2 * n + 1];
    H1[i] = fmaxf(x0 * w_in1[cc] + x1 * w_in1[C + cc] + b_in1[cc], 0.f);
    float y0 = feats[2 * n], y1 = feats[2 * n + 1];
    H2[i] = fmaxf(y0 * w_seg1[cc] + y1 * w_seg1[C + cc] + b_seg1[cc], 0.f);
}

__global__ void ew_meta(const float* __restrict__ F, const float* __restrict__ turn,
                        const float* __restrict__ control, const float* __restrict__ inter,
                        float* __restrict__ M)
{
    int n = blockIdx.x * 8 + (threadIdx.x >> 5);
    int lane = threadIdx.x & 31;
    if (n >= N_NODES) return;
    float* mp = M + (size_t)n * (C + 4);
    *(float4*)(mp + lane * 4) = *(const float4*)(F + (size_t)n * C + lane * 4);
    if (lane == 0) {
        mp[128] = turn[2 * n];
        mp[129] = turn[2 * n + 1];
        mp[130] = control[n];
        mp[131] = inter[n];
    }
}

__global__ void ew_gnrelu(const float* __restrict__ T, const float* __restrict__ g,
                          const float* __restrict__ b, float* __restrict__ X)
{
    int n = blockIdx.x * 8 + (threadIdx.x >> 5);
    int lane = threadIdx.x & 31;
    if (n >= N_NODES) return;
    float4 v = *(const float4*)(T + (size_t)n * C + lane * 4);
    float s1 = v.x + v.y + v.z + v.w;
    float s2 = v.x*v.x + v.y*v.y + v.z*v.z + v.w*v.w;
    #pragma unroll
    for (int o = 16; o >= 1; o >>= 1) {
        s1 += __shfl_xor_sync(0xffffffffu, s1, o);
        s2 += __shfl_xor_sync(0xffffffffu, s2, o);
    }
    float mu  = s1 * (1.f / 128.f);
    float var = s2 * (1.f / 128.f) - mu * mu;
    float sc  = rsqrtf(var + 1e-5f);
    float4 gv = *(const float4*)(g + lane * 4);
    float4 bv = *(const float4*)(b + lane * 4);
    float4 o;
    o.x = fmaxf((v.x - mu) * sc * gv.x + bv.x, 0.f);
    o.y = fmaxf((v.y - mu) * sc * gv.y + bv.y, 0.f);
    o.z = fmaxf((v.z - mu) * sc * gv.z + bv.z, 0.f);
    o.w = fmaxf((v.w - mu) * sc * gv.w + bv.w, 0.f);
    *(float4*)(X + (size_t)n * C + lane * 4) = o;
}

__global__ void ew_copy(const float* __restrict__ src, float* __restrict__ dst, int n) {
    int i = blockIdx.x * 256 + threadIdx.x;
    if (i < n) dst[i] = src[i];
}

// ---- host launcher ----
extern "C" void kernel_launch(void* const* d_in, const int* in_sizes, int n_in,
                              void* d_out, int out_size)
{
    const float* control  = (const float*)d_in[0];
    const float* turn     = (const float*)d_in[1];
    const float* inter    = (const float*)d_in[2];
    const float* ctrs     = (const float*)d_in[3];
    const float* feats    = (const float*)d_in[4];
    const int*   pre      = (const int*)d_in[5];
    const int*   suc      = (const int*)d_in[6];
    const int*   left     = (const int*)d_in[7];
    const int*   right    = (const int*)d_in[8];
    const float* w_in1    = (const float*)d_in[9];
    const float* b_in1    = (const float*)d_in[10];
    const float* w_in2    = (const float*)d_in[11];
    const float* gn_in_g  = (const float*)d_in[12];
    const float* gn_in_b  = (const float*)d_in[13];
    const float* w_seg1   = (const float*)d_in[14];
    const float* b_seg1   = (const float*)d_in[15];
    const float* w_seg2   = (const float*)d_in[16];
    const float* gn_seg_g = (const float*)d_in[17];
    const float* gn_seg_b = (const float*)d_in[18];
    const float* w_meta   = (const float*)d_in[19];
    const float* gn_m_g   = (const float*)d_in[20];
    const float* gn_m_b   = (const float*)d_in[21];
    const float* ctr_w    = (const float*)d_in[22];
    const float* pre_w    = (const float*)d_in[23];
    const float* suc_w    = (const float*)d_in[24];
    const float* left_w   = (const float*)d_in[25];
    const float* right_w  = (const float*)d_in[26];
    const float* norm_g   = (const float*)d_in[27];
    const float* norm_b   = (const float*)d_in[28];
    const float* ctr2_w   = (const float*)d_in[29];
    const float* ctr2_g   = (const float*)d_in[30];
    const float* ctr2_b   = (const float*)d_in[31];

    float *F, *G, *T, *X, *M;
    cudaGetSymbolAddress((void**)&F, g_F);
    cudaGetSymbolAddress((void**)&G, g_G);
    cudaGetSymbolAddress((void**)&T, g_T);
    cudaGetSymbolAddress((void**)&X, g_X);
    cudaGetSymbolAddress((void**)&M, g_M);

    const int SM128 = 128 * 192 * 4;
    const int SM132 = 132 * 192 * 4;
    cudaFuncSetAttribute(gemm_k<128,0,0,0,0,0>, cudaFuncAttributeMaxDynamicSharedMemorySize, SM128);
    cudaFuncSetAttribute(gemm_k<128,0,1,0,0,0>, cudaFuncAttributeMaxDynamicSharedMemorySize, SM128);
    cudaFuncSetAttribute(gemm_k<128,0,1,1,1,0>, cudaFuncAttributeMaxDynamicSharedMemorySize, SM128);
    cudaFuncSetAttribute(gemm_k<132,0,1,0,1,0>, cudaFuncAttributeMaxDynamicSharedMemorySize, SM132);
    cudaFuncSetAttribute(gemm_k<128,1,0,0,0,1>, cudaFuncAttributeMaxDynamicSharedMemorySize, SM128);

    const int NB = N_NODES / 64;             // 3125, exact
    const long long CC = (long long)C * C;
    const int NBP = (EP + 63) / 64;
    const int NBL = (EL + 63) / 64;

    // ---- prologue ----
    ew_in<<<(N_NODES * C + 255) / 256, 256>>>(ctrs, feats, w_in1, b_in1, w_seg1, b_seg1, X, G);
    gemm_k<128,0,1,0,0,0><<<NB, 256, SM128>>>(X, w_in2, 0, T, gn_in_g, gn_in_b,
                                              nullptr, nullptr, nullptr, 0, N_NODES);
    gemm_k<128,0,1,1,1,0><<<NB, 256, SM128>>>(G, w_seg2, 0, F, gn_seg_g, gn_seg_b,
                                              T, nullptr, nullptr, 0, N_NODES);
    ew_meta<<<N_NODES / 8, 256>>>(F, turn, control, inter, M);
    gemm_k<132,0,1,0,1,0><<<NB, 256, SM132>>>(M, w_meta, 0, F, gn_m_g, gn_m_b,
                                              nullptr, nullptr, nullptr, 0, N_NODES);

    // ---- 4 fuse layers ----
    for (int i = 0; i < 4; i++) {
        float* Fi = (i & 1) ? G : F;
        float* Fo = (i == 3) ? (float*)d_out : ((i & 1) ? F : G);

        // T = Fi @ ctr_w[i]
        gemm_k<128,0,0,0,0,0><<<NB, 256, SM128>>>(Fi, ctr_w + (size_t)i * CC, 0, T,
                                                  nullptr, nullptr, nullptr,
                                                  nullptr, nullptr, 0, N_NODES);
        // pre scales: T[dst] += Fi[src] @ pre_w[i][s]
        gemm_k<128,1,0,0,0,1><<<dim3(NBP, S), 256, SM128>>>(
            Fi, pre_w + (size_t)i * S * CC, CC, T, nullptr, nullptr, nullptr,
            pre, pre + EP, 2LL * EP, EP);
        // suc scales
        gemm_k<128,1,0,0,0,1><<<dim3(NBP, S), 256, SM128>>>(
            Fi, suc_w + (size_t)i * S * CC, CC, T, nullptr, nullptr, nullptr,
            suc, suc + EP, 2LL * EP, EP);
        // left / right
        gemm_k<128,1,0,0,0,1><<<NBL, 256, SM128>>>(
            Fi, left_w + (size_t)i * CC, 0, T, nullptr, nullptr, nullptr,
            left, left + EL, 0, EL);
        gemm_k<128,1,0,0,0,1><<<NBL, 256, SM128>>>(
            Fi, right_w + (size_t)i * CC, 0, T, nullptr, nullptr, nullptr,
            right, right + EL, 0, EL);
        // X = relu(gn(T))
        ew_gnrelu<<<N_NODES / 8, 256>>>(T, norm_g + (size_t)i * C, norm_b + (size_t)i * C, X);
        // Fo = relu(gn(X @ ctr2_w[i]) + Fi)
        gemm_k<128,0,1,1,1,0><<<NB, 256, SM128>>>(X, ctr2_w + (size_t)i * CC, 0, Fo,
                                                  ctr2_g + (size_t)i * C, ctr2_b + (size_t)i * C,
                                                  Fi, nullptr, nullptr, 0, N_NODES);
    }

    // append ctrs to output
    ew_copy<<<(N_NODES * 2 + 255) / 256, 256>>>(ctrs, (float*)d_out + (size_t)N_NODES * C,
                                                N_NODES * 2);
}

// round 4
// speedup vs baseline: 1.5273x; 1.5273x over previous
#include <cuda_runtime.h>
#include <cuda_bf16.h>
#include <cstdint>
#include <cstddef>

#define N_NODES 200000
#define C 128
#define S 6
#define EP 100000
#define EL 25000
#define CC 16384

typedef unsigned long long u64;
typedef unsigned int u32;

// ---- static device scratch ----
__device__ float g_F[(size_t)N_NODES * C];
__device__ float g_G[(size_t)N_NODES * C];
__device__ float g_T[(size_t)N_NODES * C];
__device__ float g_X[(size_t)N_NODES * C];
__device__ float g_M[(size_t)N_NODES * (C + 4)];
__device__ __nv_bfloat16 g_Fhi[(size_t)N_NODES * C];
__device__ __nv_bfloat16 g_Flo[(size_t)N_NODES * C];
__device__ __nv_bfloat16 g_Xhi[(size_t)N_NODES * C];
__device__ __nv_bfloat16 g_Xlo[(size_t)N_NODES * C];
__device__ __nv_bfloat16 g_Whi[(size_t)64 * CC];
__device__ __nv_bfloat16 g_Wlo[(size_t)64 * CC];

#define OFF_CTR   0
#define OFF_PRE   (4 * CC)
#define OFF_SUC   (28 * CC)
#define OFF_LEFT  (52 * CC)
#define OFF_RIGHT (56 * CC)
#define OFF_CTR2  (60 * CC)

// ---- helpers ----
__device__ __forceinline__ u32 cvta_sm(const void* p) {
    u32 a;
    asm("{ .reg .u64 t; cvta.to.shared.u64 t, %1; cvt.u32.u64 %0, t; }" : "=r"(a) : "l"(p));
    return a;
}
__device__ __forceinline__ void red4(float* p, float a, float b, float c, float d) {
    asm volatile("red.global.add.v4.f32 [%0], {%1,%2,%3,%4};"
                 :: "l"(p), "f"(a), "f"(b), "f"(c), "f"(d) : "memory");
}
__device__ __forceinline__ u64 dup2f(float x) {
    u64 r; u32 xi = __float_as_uint(x);
    asm("mov.b64 %0, {%1, %1};" : "=l"(r) : "r"(xi));
    return r;
}
__device__ __forceinline__ void ffma2(u64& d, u64 a, u64 b) {
    asm("fma.rn.f32x2 %0, %1, %2, %0;" : "+l"(d) : "l"(a), "l"(b));
}
__device__ __forceinline__ void unpack2f(u64 v, float& lo, float& hi) {
    u32 l, h;
    asm("mov.b64 {%0, %1}, %2;" : "=r"(l), "=r"(h) : "l"(v));
    lo = __uint_as_float(l); hi = __uint_as_float(h);
}
__device__ __forceinline__ u32 pack_bf2(float a, float b) {
    __nv_bfloat162 t = __floats2bfloat162_rn(a, b);
    return *(u32*)&t;
}

// ---- mma.sync / ldmatrix primitives (baseline PTX, sm_80+) ----
__device__ __forceinline__ void ldm4(u32* r, u32 addr) {
    asm volatile("ldmatrix.sync.aligned.m8n8.x4.shared.b16 {%0,%1,%2,%3}, [%4];"
                 : "=r"(r[0]), "=r"(r[1]), "=r"(r[2]), "=r"(r[3]) : "r"(addr));
}
__device__ __forceinline__ void mma_bf16(float* c, const u32* a, const u32* b) {
    asm volatile(
        "mma.sync.aligned.m16n8k16.row.col.f32.bf16.bf16.f32 "
        "{%0,%1,%2,%3}, {%4,%5,%6,%7}, {%8,%9}, {%0,%1,%2,%3};"
        : "+f"(c[0]), "+f"(c[1]), "+f"(c[2]), "+f"(c[3])
        : "r"(a[0]), "r"(a[1]), "r"(a[2]), "r"(a[3]), "r"(b[0]), "r"(b[1]));
}

// ---- smem layout for hmma_gemm ----
#define LDAB 144           // padded bytes per 64-bf16 staged row (conflict-free)
#define SM_AH 0
#define SM_AL 18432
#define SM_BH 36864
#define SM_BL 55296
#define SM_IDX 73728       // dst[128], src[128]
#define DSM 74752
#define LDC 132            // floats per C row in smem

// ================= bf16x3 mma.sync GEMM =================
// out[128 x 128] tile: A rows (opt. gathered) x Wt[n][k].
// EPI: 0 = store, 1 = RED scatter-add, 2 = GN + residual + relu + bf16 re-split
template<int GATHER, int EPI>
__global__ __launch_bounds__(256, 2) void hmma_gemm(
    const __nv_bfloat16* __restrict__ Ahi, const __nv_bfloat16* __restrict__ Alo,
    const __nv_bfloat16* __restrict__ Whi, const __nv_bfloat16* __restrict__ Wlo,
    long long wstride,
    float* __restrict__ out,
    const float* __restrict__ gng, const float* __restrict__ gnb,
    const float* __restrict__ addb,
    __nv_bfloat16* __restrict__ fo_hi, __nv_bfloat16* __restrict__ fo_lo,
    const int* __restrict__ dst_base, const int* __restrict__ src_base,
    long long istride, int nrows)
{
    extern __shared__ char dsm[];
    const int tid = threadIdx.x;
    const int wid = tid >> 5;
    const int lane = tid & 31;
    const int row0 = blockIdx.x * 128;

    int* s_dst = (int*)(dsm + SM_IDX);
    int* s_src = s_dst + 128;
    if (GATHER) {
        if (tid < 128) {
            int e = row0 + tid;
            const int* dp = dst_base + blockIdx.y * istride;
            const int* sp = src_base + blockIdx.y * istride;
            s_dst[tid] = (e < nrows) ? dp[e] : -1;
            s_src[tid] = (e < nrows) ? sp[e] : 0;
        }
        __syncthreads();
    }

    const __nv_bfloat16* WH = Whi + (long long)blockIdx.y * wstride;
    const __nv_bfloat16* WL = Wlo + (long long)blockIdx.y * wstride;
    const u32 smb = cvta_sm(dsm);

    const int wm = (wid & 3) * 32;   // warp row tile
    const int wn = (wid >> 2) * 64;  // warp col tile

    float acc[2][8][4];
    #pragma unroll
    for (int mi = 0; mi < 2; mi++)
        #pragma unroll
        for (int nj = 0; nj < 8; nj++)
            #pragma unroll
            for (int q = 0; q < 4; q++) acc[mi][nj][q] = 0.f;

    // per-thread ldmatrix base offsets
    const u32 a_off = (u32)(wm + (lane & 15)) * LDAB + (u32)(lane >> 4) * 16;
    const u32 b_off = (u32)(wn + (lane & 7) + ((lane >> 4) & 1) * 8) * LDAB
                    + (u32)((lane >> 3) & 1) * 16;

    for (int kh = 0; kh < 2; kh++) {
        if (kh) __syncthreads();
        // stage 4 tiles: 128 rows x 64 bf16 (128B), padded to 144B rows
        #pragma unroll
        for (int i = 0; i < 4; i++) {
            int v = tid + i * 256;          // 0..1023
            int r = v >> 3, cq = v & 7;
            u32 doff = (u32)r * LDAB + (u32)cq * 16;
            uint4 ah = make_uint4(0, 0, 0, 0), al = make_uint4(0, 0, 0, 0);
            if (GATHER) {
                size_t so = (size_t)s_src[r] * 256 + (size_t)kh * 128 + (size_t)cq * 16;
                ah = *(const uint4*)((const char*)Ahi + so);
                al = *(const uint4*)((const char*)Alo + so);
            } else {
                int gr = row0 + r;
                if (gr < nrows) {
                    size_t so = (size_t)gr * 256 + (size_t)kh * 128 + (size_t)cq * 16;
                    ah = *(const uint4*)((const char*)Ahi + so);
                    al = *(const uint4*)((const char*)Alo + so);
                }
            }
            *(uint4*)(dsm + SM_AH + doff) = ah;
            *(uint4*)(dsm + SM_AL + doff) = al;
            size_t wo = (size_t)r * 256 + (size_t)kh * 128 + (size_t)cq * 16;
            *(uint4*)(dsm + SM_BH + doff) = *(const uint4*)((const char*)WH + wo);
            *(uint4*)(dsm + SM_BL + doff) = *(const uint4*)((const char*)WL + wo);
        }
        __syncthreads();

        // 3 passes: Ah*Bh, Ah*Bl, Al*Bh
        #pragma unroll
        for (int pass = 0; pass < 3; pass++) {
            const u32 abase = smb + (pass == 2 ? SM_AL : SM_AH) + a_off;
            const u32 bbase = smb + (pass == 1 ? SM_BL : SM_BH) + b_off;
            #pragma unroll
            for (int ks = 0; ks < 4; ks++) {
                u32 a[2][4], b[4][4];
                ldm4(a[0], abase + ks * 32);
                ldm4(a[1], abase + 16 * LDAB + ks * 32);
                #pragma unroll
                for (int ni = 0; ni < 4; ni++)
                    ldm4(b[ni], bbase + ni * 16 * LDAB + ks * 32);
                #pragma unroll
                for (int mi = 0; mi < 2; mi++)
                    #pragma unroll
                    for (int ni = 0; ni < 4; ni++) {
                        mma_bf16(acc[mi][2 * ni],     a[mi], &b[ni][0]);
                        mma_bf16(acc[mi][2 * ni + 1], a[mi], &b[ni][2]);
                    }
            }
        }
    }

    // ---- write accumulators to smem C tile (aliases staging buffers) ----
    __syncthreads();
    float* Csm = (float*)dsm;
    #pragma unroll
    for (int mi = 0; mi < 2; mi++)
        #pragma unroll
        for (int nj = 0; nj < 8; nj++) {
            int r = wm + mi * 16 + (lane >> 2);
            int c = wn + nj * 8 + (lane & 3) * 2;
            float* p = Csm + (size_t)r * LDC + c;
            p[0] = acc[mi][nj][0];
            p[1] = acc[mi][nj][1];
            p[8 * LDC] = acc[mi][nj][2];
            p[8 * LDC + 1] = acc[mi][nj][3];
        }
    __syncthreads();

    // ---- row-wise epilogue: warp handles 16 rows ----
    for (int i = 0; i < 16; i++) {
        int r = wid * 16 + i;
        float4 v = *(float4*)(Csm + (size_t)r * LDC + lane * 4);
        if (EPI == 1) {
            int dd = s_dst[r];
            if (dd >= 0)
                red4(out + (size_t)dd * C + lane * 4, v.x, v.y, v.z, v.w);
        } else {
            int row = row0 + r;
            if (row < nrows) {
                if (EPI == 2) {
                    float s1 = v.x + v.y + v.z + v.w;
                    float s2 = v.x*v.x + v.y*v.y + v.z*v.z + v.w*v.w;
                    #pragma unroll
                    for (int o = 16; o >= 1; o >>= 1) {
                        s1 += __shfl_xor_sync(0xffffffffu, s1, o);
                        s2 += __shfl_xor_sync(0xffffffffu, s2, o);
                    }
                    float mu = s1 * (1.f / 128.f);
                    float var = s2 * (1.f / 128.f) - mu * mu;
                    float rs = rsqrtf(var + 1e-5f);
                    float4 gv = *(const float4*)(gng + lane * 4);
                    float4 bv = *(const float4*)(gnb + lane * 4);
                    float4 rr = *(const float4*)(addb + (size_t)row * C + lane * 4);
                    float v0 = fmaxf((v.x - mu) * rs * gv.x + bv.x + rr.x, 0.f);
                    float v1 = fmaxf((v.y - mu) * rs * gv.y + bv.y + rr.y, 0.f);
                    float v2 = fmaxf((v.z - mu) * rs * gv.z + bv.z + rr.z, 0.f);
                    float v3 = fmaxf((v.w - mu) * rs * gv.w + bv.w + rr.w, 0.f);
                    *(float4*)(out + (size_t)row * C + lane * 4) =
                        make_float4(v0, v1, v2, v3);
                    // bf16 hi/lo re-split for next layer
                    __nv_bfloat16 h0 = __float2bfloat16(v0), h1 = __float2bfloat16(v1);
                    __nv_bfloat16 h2 = __float2bfloat16(v2), h3 = __float2bfloat16(v3);
                    uint2 H, L;
                    H.x = pack_bf2(__bfloat162float(h0), __bfloat162float(h1));
                    H.y = pack_bf2(__bfloat162float(h2), __bfloat162float(h3));
                    // pack hi directly from the bf16 values
                    __nv_bfloat162 hh0; hh0.x = h0; hh0.y = h1;
                    __nv_bfloat162 hh1; hh1.x = h2; hh1.y = h3;
                    H.x = *(u32*)&hh0; H.y = *(u32*)&hh1;
                    L.x = pack_bf2(v0 - __bfloat162float(h0), v1 - __bfloat162float(h1));
                    L.y = pack_bf2(v2 - __bfloat162float(h2), v3 - __bfloat162float(h3));
                    *(uint2*)((char*)fo_hi + ((size_t)row * C + lane * 4) * 2) = H;
                    *(uint2*)((char*)fo_lo + ((size_t)row * C + lane * 4) * 2) = L;
                } else {
                    *(float4*)(out + (size_t)row * C + lane * 4) = v;
                }
            }
        }
    }
}

// ================= FFMA2 GEMM (prologue only, with GN) =================
template<int K, int DOADD, int DORELU>
__global__ __launch_bounds__(256, 2) void gemm_k(
    const float* __restrict__ A, const float* __restrict__ W,
    float* __restrict__ out,
    const float* __restrict__ gng, const float* __restrict__ gnb,
    const float* __restrict__ addb, int nrows)
{
    extern __shared__ float sm[];
    float* As = sm;
    float* Ws = sm + K * 64;
    const int tid = threadIdx.x;
    const int row0 = blockIdx.x * 64;

    for (int v = tid; v < K * 32; v += 256)
        *(float4*)(Ws + (size_t)v * 4) = *(const float4*)(W + (size_t)v * 4);
    for (int v = tid; v < 64 * (K / 4); v += 256) {
        int m = v & 63, kq = v >> 6;
        float4 a = make_float4(0.f, 0.f, 0.f, 0.f);
        int row = row0 + m;
        if (row < nrows) a = *(const float4*)(A + (size_t)row * K + kq * 4);
        As[(4*kq+0)*64+m] = a.x; As[(4*kq+1)*64+m] = a.y;
        As[(4*kq+2)*64+m] = a.z; As[(4*kq+3)*64+m] = a.w;
    }
    __syncthreads();

    const int tc = tid & 31, tr = tid >> 5;
    u64 acc[8][2];
    #pragma unroll
    for (int i = 0; i < 8; i++) { acc[i][0] = 0ULL; acc[i][1] = 0ULL; }
    const float* ap = As + tr * 8;
    const float* bp = Ws + tc * 4;

    #pragma unroll 4
    for (int k = 0; k < K; k++) {
        float4 a0 = *(const float4*)(ap + (size_t)k * 64);
        float4 a1 = *(const float4*)(ap + (size_t)k * 64 + 4);
        ulonglong2 b = *(const ulonglong2*)(bp + (size_t)k * 128);
        u64 av;
        av = dup2f(a0.x); ffma2(acc[0][0], av, b.x); ffma2(acc[0][1], av, b.y);
        av = dup2f(a0.y); ffma2(acc[1][0], av, b.x); ffma2(acc[1][1], av, b.y);
        av = dup2f(a0.z); ffma2(acc[2][0], av, b.x); ffma2(acc[2][1], av, b.y);
        av = dup2f(a0.w); ffma2(acc[3][0], av, b.x); ffma2(acc[3][1], av, b.y);
        av = dup2f(a1.x); ffma2(acc[4][0], av, b.x); ffma2(acc[4][1], av, b.y);
        av = dup2f(a1.y); ffma2(acc[5][0], av, b.x); ffma2(acc[5][1], av, b.y);
        av = dup2f(a1.z); ffma2(acc[6][0], av, b.x); ffma2(acc[6][1], av, b.y);
        av = dup2f(a1.w); ffma2(acc[7][0], av, b.x); ffma2(acc[7][1], av, b.y);
    }

    float c[8][4];
    #pragma unroll
    for (int mi = 0; mi < 8; mi++) {
        unpack2f(acc[mi][0], c[mi][0], c[mi][1]);
        unpack2f(acc[mi][1], c[mi][2], c[mi][3]);
    }
    float gg[4], bb[4];
    *(float4*)gg = *(const float4*)(gng + tc * 4);
    *(float4*)bb = *(const float4*)(gnb + tc * 4);
    #pragma unroll
    for (int mi = 0; mi < 8; mi++) {
        float s1 = c[mi][0]+c[mi][1]+c[mi][2]+c[mi][3];
        float s2 = c[mi][0]*c[mi][0]+c[mi][1]*c[mi][1]+c[mi][2]*c[mi][2]+c[mi][3]*c[mi][3];
        #pragma unroll
        for (int o = 16; o >= 1; o >>= 1) {
            s1 += __shfl_xor_sync(0xffffffffu, s1, o);
            s2 += __shfl_xor_sync(0xffffffffu, s2, o);
        }
        float mu = s1 * (1.f/128.f);
        float var = s2 * (1.f/128.f) - mu * mu;
        float sc = rsqrtf(var + 1e-5f);
        #pragma unroll
        for (int j = 0; j < 4; j++)
            c[mi][j] = (c[mi][j] - mu) * sc * gg[j] + bb[j];
    }
    #pragma unroll
    for (int mi = 0; mi < 8; mi++) {
        int row = row0 + tr * 8 + mi;
        if (row < nrows) {
            if (DOADD) {
                float4 r = *(const float4*)(addb + (size_t)row * C + tc * 4);
                c[mi][0] += r.x; c[mi][1] += r.y; c[mi][2] += r.z; c[mi][3] += r.w;
            }
            if (DORELU) {
                #pragma unroll
                for (int j = 0; j < 4; j++) c[mi][j] = fmaxf(c[mi][j], 0.f);
            }
            *(float4*)(out + (size_t)row * C + tc * 4) =
                make_float4(c[mi][0], c[mi][1], c[mi][2], c[mi][3]);
        }
    }
}

// ================= small kernels =================
__global__ void wsplit(const float* __restrict__ src, __nv_bfloat16* __restrict__ hi,
                       __nv_bfloat16* __restrict__ lo, int total)
{
    int idx = blockIdx.x * 256 + threadIdx.x;
    if (idx >= total) return;
    int mat = idx >> 14;
    int rem = idx & 16383;
    int k = rem >> 7, n = rem & 127;
    float x = src[idx];
    __nv_bfloat16 h = __float2bfloat16(x);
    float l = x - __bfloat162float(h);
    int o = (mat << 14) + n * C + k;   // transpose: Wt[n][k]
    hi[o] = h; lo[o] = __float2bfloat16(l);
}

__global__ void fsplit(const float* __restrict__ src, __nv_bfloat16* __restrict__ hi,
                       __nv_bfloat16* __restrict__ lo)
{
    int i = blockIdx.x * 256 + threadIdx.x;   // float4 index
    float4 v = ((const float4*)src)[i];
    __nv_bfloat16 h0 = __float2bfloat16(v.x), h1 = __float2bfloat16(v.y);
    __nv_bfloat16 h2 = __float2bfloat16(v.z), h3 = __float2bfloat16(v.w);
    __nv_bfloat162 hh0; hh0.x = h0; hh0.y = h1;
    __nv_bfloat162 hh1; hh1.x = h2; hh1.y = h3;
    uint2 H; H.x = *(u32*)&hh0; H.y = *(u32*)&hh1;
    uint2 L;
    L.x = pack_bf2(v.x - __bfloat162float(h0), v.y - __bfloat162float(h1));
    L.y = pack_bf2(v.z - __bfloat162float(h2), v.w - __bfloat162float(h3));
    ((uint2*)hi)[i] = H;
    ((uint2*)lo)[i] = L;
}

__global__ void ew_in(const float* __restrict__ ctrs, const float* __restrict__ feats,
                      const float* __restrict__ w_in1, const float* __restrict__ b_in1,
                      const float* __restrict__ w_seg1, const float* __restrict__ b_seg1,
                      float* __restrict__ H1, float* __restrict__ H2)
{
    int i = blockIdx.x * 256 + threadIdx.x;
    if (i >= N_NODES * C) return;
    int n = i >> 7, cc = i & 127;
    float x0 = ctrs[2*n], x1 = ctrs[2*n+1];
    H1[i] = fmaxf(x0 * w_in1[cc] + x1 * w_in1[C+cc] + b_in1[cc], 0.f);
    float y0 = feats[2*n], y1 = feats[2*n+1];
    H2[i] = fmaxf(y0 * w_seg1[cc] + y1 * w_seg1[C+cc] + b_seg1[cc], 0.f);
}

__global__ void ew_meta(const float* __restrict__ F, const float* __restrict__ turn,
                        const float* __restrict__ control, const float* __restrict__ inter,
                        float* __restrict__ M)
{
    int n = blockIdx.x * 8 + (threadIdx.x >> 5);
    int lane = threadIdx.x & 31;
    if (n >= N_NODES) return;
    float* mp = M + (size_t)n * (C + 4);
    *(float4*)(mp + lane * 4) = *(const float4*)(F + (size_t)n * C + lane * 4);
    if (lane == 0) {
        mp[128] = turn[2*n]; mp[129] = turn[2*n+1];
        mp[130] = control[n]; mp[131] = inter[n];
    }
}

__global__ void ew_gnrelu_split(const float* __restrict__ T, const float* __restrict__ g,
                                const float* __restrict__ b,
                                __nv_bfloat16* __restrict__ Xhi,
                                __nv_bfloat16* __restrict__ Xlo)
{
    int n = blockIdx.x * 8 + (threadIdx.x >> 5);
    int lane = threadIdx.x & 31;
    if (n >= N_NODES) return;
    float4 v = *(const float4*)(T + (size_t)n * C + lane * 4);
    float s1 = v.x + v.y + v.z + v.w;
    float s2 = v.x*v.x + v.y*v.y + v.z*v.z + v.w*v.w;
    #pragma unroll
    for (int o = 16; o >= 1; o >>= 1) {
        s1 += __shfl_xor_sync(0xffffffffu, s1, o);
        s2 += __shfl_xor_sync(0xffffffffu, s2, o);
    }
    float mu = s1 * (1.f/128.f);
    float var = s2 * (1.f/128.f) - mu * mu;
    float sc = rsqrtf(var + 1e-5f);
    float4 gv = *(const float4*)(g + lane * 4);
    float4 bv = *(const float4*)(b + lane * 4);
    float v0 = fmaxf((v.x - mu) * sc * gv.x + bv.x, 0.f);
    float v1 = fmaxf((v.y - mu) * sc * gv.y + bv.y, 0.f);
    float v2 = fmaxf((v.z - mu) * sc * gv.z + bv.z, 0.f);
    float v3 = fmaxf((v.w - mu) * sc * gv.w + bv.w, 0.f);
    __nv_bfloat16 h0 = __float2bfloat16(v0), h1 = __float2bfloat16(v1);
    __nv_bfloat16 h2 = __float2bfloat16(v2), h3 = __float2bfloat16(v3);
    __nv_bfloat162 hh0; hh0.x = h0; hh0.y = h1;
    __nv_bfloat162 hh1; hh1.x = h2; hh1.y = h3;
    uint2 H; H.x = *(u32*)&hh0; H.y = *(u32*)&hh1;
    uint2 L;
    L.x = pack_bf2(v0 - __bfloat162float(h0), v1 - __bfloat162float(h1));
    L.y = pack_bf2(v2 - __bfloat162float(h2), v3 - __bfloat162float(h3));
    size_t off = (size_t)n * 32 + lane;
    ((uint2*)Xhi)[off] = H;
    ((uint2*)Xlo)[off] = L;
}

__global__ void ew_copy(const float* __restrict__ src, float* __restrict__ dst, int n) {
    int i = blockIdx.x * 256 + threadIdx.x;
    if (i < n) dst[i] = src[i];
}

// ================= host launcher =================
extern "C" void kernel_launch(void* const* d_in, const int* in_sizes, int n_in,
                              void* d_out, int out_size)
{
    const float* control  = (const float*)d_in[0];
    const float* turn     = (const float*)d_in[1];
    const float* inter    = (const float*)d_in[2];
    const float* ctrs     = (const float*)d_in[3];
    const float* feats    = (const float*)d_in[4];
    const int*   pre      = (const int*)d_in[5];
    const int*   suc      = (const int*)d_in[6];
    const int*   left     = (const int*)d_in[7];
    const int*   right    = (const int*)d_in[8];
    const float* w_in1    = (const float*)d_in[9];
    const float* b_in1    = (const float*)d_in[10];
    const float* w_in2    = (const float*)d_in[11];
    const float* gn_in_g  = (const float*)d_in[12];
    const float* gn_in_b  = (const float*)d_in[13];
    const float* w_seg1   = (const float*)d_in[14];
    const float* b_seg1   = (const float*)d_in[15];
    const float* w_seg2   = (const float*)d_in[16];
    const float* gn_seg_g = (const float*)d_in[17];
    const float* gn_seg_b = (const float*)d_in[18];
    const float* w_meta   = (const float*)d_in[19];
    const float* gn_m_g   = (const float*)d_in[20];
    const float* gn_m_b   = (const float*)d_in[21];
    const float* ctr_w    = (const float*)d_in[22];
    const float* pre_w    = (const float*)d_in[23];
    const float* suc_w    = (const float*)d_in[24];
    const float* left_w   = (const float*)d_in[25];
    const float* right_w  = (const float*)d_in[26];
    const float* norm_g   = (const float*)d_in[27];
    const float* norm_b   = (const float*)d_in[28];
    const float* ctr2_w   = (const float*)d_in[29];
    const float* ctr2_g   = (const float*)d_in[30];
    const float* ctr2_b   = (const float*)d_in[31];

    float *F, *G, *T, *X, *M;
    __nv_bfloat16 *Fhi, *Flo, *Xhi, *Xlo, *Whi, *Wlo;
    cudaGetSymbolAddress((void**)&F, g_F);
    cudaGetSymbolAddress((void**)&G, g_G);
    cudaGetSymbolAddress((void**)&T, g_T);
    cudaGetSymbolAddress((void**)&X, g_X);
    cudaGetSymbolAddress((void**)&M, g_M);
    cudaGetSymbolAddress((void**)&Fhi, g_Fhi);
    cudaGetSymbolAddress((void**)&Flo, g_Flo);
    cudaGetSymbolAddress((void**)&Xhi, g_Xhi);
    cudaGetSymbolAddress((void**)&Xlo, g_Xlo);
    cudaGetSymbolAddress((void**)&Whi, g_Whi);
    cudaGetSymbolAddress((void**)&Wlo, g_Wlo);

    const int SM128 = 128 * 192 * 4;
    const int SM132 = 132 * 192 * 4;
    cudaFuncSetAttribute(gemm_k<128,0,0>, cudaFuncAttributeMaxDynamicSharedMemorySize, SM128);
    cudaFuncSetAttribute(gemm_k<128,1,1>, cudaFuncAttributeMaxDynamicSharedMemorySize, SM128);
    cudaFuncSetAttribute(gemm_k<132,0,1>, cudaFuncAttributeMaxDynamicSharedMemorySize, SM132);
    cudaFuncSetAttribute(hmma_gemm<0,0>, cudaFuncAttributeMaxDynamicSharedMemorySize, DSM);
    cudaFuncSetAttribute(hmma_gemm<1,1>, cudaFuncAttributeMaxDynamicSharedMemorySize, DSM);
    cudaFuncSetAttribute(hmma_gemm<0,2>, cudaFuncAttributeMaxDynamicSharedMemorySize, DSM);

    const int NB64 = (N_NODES + 63) / 64;
    const int NB = (N_NODES + 127) / 128;
    const int NBP = (EP + 127) / 128;
    const int NBL = (EL + 127) / 128;

    // split weights (tf-style bf16 hi/lo) + transpose to Wt[n][k]
    wsplit<<<4*CC/256, 256>>>(ctr_w,   Whi + OFF_CTR,   Wlo + OFF_CTR,   4*CC);
    wsplit<<<24*CC/256,256>>>(pre_w,   Whi + OFF_PRE,   Wlo + OFF_PRE,   24*CC);
    wsplit<<<24*CC/256,256>>>(suc_w,   Whi + OFF_SUC,   Wlo + OFF_SUC,   24*CC);
    wsplit<<<4*CC/256, 256>>>(left_w,  Whi + OFF_LEFT,  Wlo + OFF_LEFT,  4*CC);
    wsplit<<<4*CC/256, 256>>>(right_w, Whi + OFF_RIGHT, Wlo + OFF_RIGHT, 4*CC);
    wsplit<<<4*CC/256, 256>>>(ctr2_w,  Whi + OFF_CTR2,  Wlo + OFF_CTR2,  4*CC);

    // prologue (FFMA2, fp32)
    ew_in<<<(N_NODES*C+255)/256, 256>>>(ctrs, feats, w_in1, b_in1, w_seg1, b_seg1, X, G);
    gemm_k<128,0,0><<<NB64, 256, SM128>>>(X, w_in2, T, gn_in_g, gn_in_b, nullptr, N_NODES);
    gemm_k<128,1,1><<<NB64, 256, SM128>>>(G, w_seg2, F, gn_seg_g, gn_seg_b, T, N_NODES);
    ew_meta<<<N_NODES/8, 256>>>(F, turn, control, inter, M);
    gemm_k<132,0,1><<<NB64, 256, SM132>>>(M, w_meta, F, gn_m_g, gn_m_b, nullptr, N_NODES);
    fsplit<<<N_NODES*C/4/256, 256>>>(F, Fhi, Flo);

    // 4 fuse layers (mma.sync bf16x3)
    for (int i = 0; i < 4; i++) {
        float* Fi = (i & 1) ? G : F;
        float* Fo = (i == 3) ? (float*)d_out : ((i & 1) ? F : G);

        hmma_gemm<0,0><<<NB, 256, DSM>>>(
            Fhi, Flo, Whi + OFF_CTR + (size_t)i*CC, Wlo + OFF_CTR + (size_t)i*CC, 0,
            T, nullptr, nullptr, nullptr, nullptr, nullptr, nullptr, nullptr, 0, N_NODES);
        hmma_gemm<1,1><<<dim3(NBP, S), 256, DSM>>>(
            Fhi, Flo, Whi + OFF_PRE + (size_t)i*S*CC, Wlo + OFF_PRE + (size_t)i*S*CC, CC,
            T, nullptr, nullptr, nullptr, nullptr, nullptr, pre, pre + EP, 2LL*EP, EP);
        hmma_gemm<1,1><<<dim3(NBP, S), 256, DSM>>>(
            Fhi, Flo, Whi + OFF_SUC + (size_t)i*S*CC, Wlo + OFF_SUC + (size_t)i*S*CC, CC,
            T, nullptr, nullptr, nullptr, nullptr, nullptr, suc, suc + EP, 2LL*EP, EP);
        hmma_gemm<1,1><<<NBL, 256, DSM>>>(
            Fhi, Flo, Whi + OFF_LEFT + (size_t)i*CC, Wlo + OFF_LEFT + (size_t)i*CC, 0,
            T, nullptr, nullptr, nullptr, nullptr, nullptr, left, left + EL, 0, EL);
        hmma_gemm<1,1><<<NBL, 256, DSM>>>(
            Fhi, Flo, Whi + OFF_RIGHT + (size_t)i*CC, Wlo + OFF_RIGHT + (size_t)i*CC, 0,
            T, nullptr, nullptr, nullptr, nullptr, nullptr, right, right + EL, 0, EL);
        ew_gnrelu_split<<<N_NODES/8, 256>>>(T, norm_g + (size_t)i*C, norm_b + (size_t)i*C,
                                            Xhi, Xlo);
        hmma_gemm<0,2><<<NB, 256, DSM>>>(
            Xhi, Xlo, Whi + OFF_CTR2 + (size_t)i*CC, Wlo + OFF_CTR2 + (size_t)i*CC, 0,
            Fo, ctr2_g + (size_t)i*C, ctr2_b + (size_t)i*C, Fi,
            Fhi, Flo, nullptr, nullptr, 0, N_NODES);
    }

    ew_copy<<<(N_NODES*2+255)/256, 256>>>(ctrs, (float*)d_out + (size_t)N_NODES*C, N_NODES*2);
}

// round 5
// speedup vs baseline: 2.2338x; 1.4626x over previous
#include <cuda_runtime.h>
#include <cuda_bf16.h>
#include <cstdint>
#include <cstddef>

#define N_NODES 200000
#define C 128
#define S 6
#define EP 100000
#define EL 25000
#define CC 16384

typedef unsigned long long u64;
typedef unsigned int u32;

// ---- static device scratch ----
__device__ float g_F[(size_t)N_NODES * C];
__device__ float g_G[(size_t)N_NODES * C];
__device__ float g_T[(size_t)N_NODES * C];
__device__ __nv_bfloat16 g_Fhi[(size_t)N_NODES * C];
__device__ __nv_bfloat16 g_Flo[(size_t)N_NODES * C];
__device__ __nv_bfloat16 g_Xhi[(size_t)N_NODES * C];
__device__ __nv_bfloat16 g_Xlo[(size_t)N_NODES * C];
__device__ __nv_bfloat16 g_Whi[(size_t)67 * CC];
__device__ __nv_bfloat16 g_Wlo[(size_t)67 * CC];

// weight slots (transposed Wt[n][k], bf16 hi/lo)
#define OFF_IN2   0
#define OFF_SEG2  (1 * CC)
#define OFF_META  (2 * CC)
#define OFF_CTR   (3 * CC)
#define OFF_PRE   (7 * CC)
#define OFF_SUC   (31 * CC)
#define OFF_LEFT  (55 * CC)
#define OFF_RIGHT (59 * CC)
#define OFF_CTR2  (63 * CC)

// ---- helpers ----
__device__ __forceinline__ u32 cvta_sm(const void* p) {
    u32 a;
    asm("{ .reg .u64 t; cvta.to.shared.u64 t, %1; cvt.u32.u64 %0, t; }" : "=r"(a) : "l"(p));
    return a;
}
__device__ __forceinline__ void red4(float* p, float a, float b, float c, float d) {
    asm volatile("red.global.add.v4.f32 [%0], {%1,%2,%3,%4};"
                 :: "l"(p), "f"(a), "f"(b), "f"(c), "f"(d) : "memory");
}
__device__ __forceinline__ u32 pack_bf2(float a, float b) {
    __nv_bfloat162 t = __floats2bfloat162_rn(a, b);
    return *(u32*)&t;
}
__device__ __forceinline__ void ldm4(u32* r, u32 addr) {
    asm volatile("ldmatrix.sync.aligned.m8n8.x4.shared.b16 {%0,%1,%2,%3}, [%4];"
                 : "=r"(r[0]), "=r"(r[1]), "=r"(r[2]), "=r"(r[3]) : "r"(addr));
}
__device__ __forceinline__ void mma_bf16(float* c, const u32* a, const u32* b) {
    asm volatile(
        "mma.sync.aligned.m16n8k16.row.col.f32.bf16.bf16.f32 "
        "{%0,%1,%2,%3}, {%4,%5,%6,%7}, {%8,%9}, {%0,%1,%2,%3};"
        : "+f"(c[0]), "+f"(c[1]), "+f"(c[2]), "+f"(c[3])
        : "r"(a[0]), "r"(a[1]), "r"(a[2]), "r"(a[3]), "r"(b[0]), "r"(b[1]));
}
__device__ __forceinline__ void cpa16(u32 dst, const void* src, u32 sz) {
    asm volatile("cp.async.cg.shared.global [%0], [%1], 16, %2;"
                 :: "r"(dst), "l"(src), "r"(sz) : "memory");
}
#define CP_COMMIT() asm volatile("cp.async.commit_group;" ::: "memory")

// ---- hmma smem layout (quarter-pipelined) ----
#define LDQ   80                 // padded bytes per 32-bf16 row
#define OFF_AH 0
#define OFF_AL 10240
#define OFF_BH 20480
#define OFF_BL 30720
#define QSET  40960              // one quarter set (4 matrices)
#define SM_IDX 81920             // dst[128], src[128]
#define DSM   82944
#define LDC   132                // floats per row of smem C tile

template<int GATHER>
__device__ __forceinline__ void stage_q(
    u32 smb, int q, int bi, int tid, int row0, int nrows, const int* s_src,
    const __nv_bfloat16* Ahi, const __nv_bfloat16* Alo,
    const __nv_bfloat16* WH, const __nv_bfloat16* WL)
{
    u32 bbase = smb + (u32)bi * QSET;
    #pragma unroll
    for (int j = 0; j < 2; j++) {
        int id = tid + j * 256;       // 0..511
        int r = id >> 2, sg = id & 3;
        u32 doff = (u32)r * LDQ + (u32)sg * 16;
        u32 asz = 16;
        long long arow;
        if (GATHER) {
            arow = s_src[r];
        } else {
            int gr = row0 + r;
            if (gr >= nrows) { asz = 0; gr = 0; }
            arow = gr;
        }
        size_t abyte = (size_t)arow * 256 + (size_t)q * 64 + (size_t)sg * 16;
        cpa16(bbase + OFF_AH + doff, (const char*)Ahi + abyte, asz);
        cpa16(bbase + OFF_AL + doff, (const char*)Alo + abyte, asz);
        size_t wbyte = (size_t)r * 256 + (size_t)q * 64 + (size_t)sg * 16;
        cpa16(bbase + OFF_BH + doff, (const char*)WH + wbyte, 16);
        cpa16(bbase + OFF_BL + doff, (const char*)WL + wbyte, 16);
    }
    CP_COMMIT();
}

// ================= bf16x3 mma.sync GEMM, cp.async pipelined =================
// EPI: 0 store | 1 RED scatter | 2 GN+add+relu+split | 3 extras+GN+relu+split | 4 GN only
template<int GATHER, int EPI>
__global__ __launch_bounds__(256, 2) void hmma_gemm(
    const __nv_bfloat16* __restrict__ Ahi, const __nv_bfloat16* __restrict__ Alo,
    const __nv_bfloat16* __restrict__ Whi, const __nv_bfloat16* __restrict__ Wlo,
    long long wstride,
    float* __restrict__ out,
    const float* __restrict__ gng, const float* __restrict__ gnb,
    const float* __restrict__ addb,
    __nv_bfloat16* __restrict__ fo_hi, __nv_bfloat16* __restrict__ fo_lo,
    const int* __restrict__ dst_base, const int* __restrict__ src_base,
    long long istride, int nrows,
    const float* __restrict__ turn, const float* __restrict__ control,
    const float* __restrict__ inter, const float* __restrict__ wext)
{
    extern __shared__ char dsm[];
    const int tid = threadIdx.x;
    const int wid = tid >> 5;
    const int lane = tid & 31;
    const int row0 = blockIdx.x * 128;
    const u32 smb = cvta_sm(dsm);

    int* s_dst = (int*)(dsm + SM_IDX);
    int* s_src = s_dst + 128;
    if (GATHER) {
        if (tid < 128) {
            int e = row0 + tid;
            const int* dp = dst_base + blockIdx.y * istride;
            const int* sp = src_base + blockIdx.y * istride;
            s_dst[tid] = (e < nrows) ? dp[e] : -1;
            s_src[tid] = (e < nrows) ? sp[e] : 0;
        }
        __syncthreads();
    }

    const __nv_bfloat16* WH = Whi + (long long)blockIdx.y * wstride;
    const __nv_bfloat16* WL = Wlo + (long long)blockIdx.y * wstride;

    const int wm = (wid & 3) * 32;
    const int wn = (wid >> 2) * 64;

    float acc[2][8][4];
    #pragma unroll
    for (int mi = 0; mi < 2; mi++)
        #pragma unroll
        for (int nj = 0; nj < 8; nj++)
            #pragma unroll
            for (int q = 0; q < 4; q++) acc[mi][nj][q] = 0.f;

    const u32 a_off = (u32)(wm + (lane & 15)) * LDQ + (u32)(lane >> 4) * 16;
    const u32 b_off = (u32)(wn + (lane & 7) + ((lane >> 4) & 1) * 8) * LDQ
                    + (u32)((lane >> 3) & 1) * 16;

    stage_q<GATHER>(smb, 0, 0, tid, row0, nrows, s_src, Ahi, Alo, WH, WL);
    stage_q<GATHER>(smb, 1, 1, tid, row0, nrows, s_src, Ahi, Alo, WH, WL);

#define MMAS(A, B) do {                                                        \
    _Pragma("unroll") for (int mi = 0; mi < 2; mi++)                           \
        _Pragma("unroll") for (int ni = 0; ni < 4; ni++) {                     \
            mma_bf16(acc[mi][2 * ni],     (A)[mi], &(B)[ni][0]);               \
            mma_bf16(acc[mi][2 * ni + 1], (A)[mi], &(B)[ni][2]);               \
        }                                                                      \
} while (0)

    #pragma unroll
    for (int q = 0; q < 4; q++) {
        if (q == 3) asm volatile("cp.async.wait_group 0;" ::: "memory");
        else        asm volatile("cp.async.wait_group 1;" ::: "memory");
        __syncthreads();

        const u32 qb = smb + (u32)(q & 1) * QSET;
        #pragma unroll
        for (int ks = 0; ks < 2; ks++) {
            u32 a0[2][4], a1[2][4], b0[4][4], b1[4][4];
            u32 ab = qb + OFF_AH + a_off + ks * 32;
            ldm4(a0[0], ab); ldm4(a0[1], ab + 16 * LDQ);
            u32 bb = qb + OFF_BH + b_off + ks * 32;
            #pragma unroll
            for (int ni = 0; ni < 4; ni++) ldm4(b0[ni], bb + ni * 16 * LDQ);
            MMAS(a0, b0);                       // Ah*Bh
            u32 alb = qb + OFF_AL + a_off + ks * 32;
            ldm4(a1[0], alb); ldm4(a1[1], alb + 16 * LDQ);
            MMAS(a1, b0);                       // Al*Bh
            u32 blb = qb + OFF_BL + b_off + ks * 32;
            #pragma unroll
            for (int ni = 0; ni < 4; ni++) ldm4(b1[ni], blb + ni * 16 * LDQ);
            MMAS(a0, b1);                       // Ah*Bl
        }

        if (q < 2) {
            __syncthreads();   // all warps done reading buf[q&1] before restage
            stage_q<GATHER>(smb, q + 2, q & 1, tid, row0, nrows, s_src, Ahi, Alo, WH, WL);
        }
    }
#undef MMAS

    // ---- accumulators -> smem C tile ----
    __syncthreads();
    float* Csm = (float*)dsm;
    #pragma unroll
    for (int mi = 0; mi < 2; mi++)
        #pragma unroll
        for (int nj = 0; nj < 8; nj++) {
            int r = wm + mi * 16 + (lane >> 2);
            int c = wn + nj * 8 + (lane & 3) * 2;
            float* p = Csm + (size_t)r * LDC + c;
            p[0] = acc[mi][nj][0];
            p[1] = acc[mi][nj][1];
            p[8 * LDC] = acc[mi][nj][2];
            p[8 * LDC + 1] = acc[mi][nj][3];
        }
    __syncthreads();

    // ---- row-wise epilogue: each warp owns 16 full rows ----
    float4 gv, bv;
    float4 we[4];
    if (EPI == 2 || EPI == 3 || EPI == 4) {
        gv = *(const float4*)(gng + lane * 4);
        bv = *(const float4*)(gnb + lane * 4);
    }
    if (EPI == 3) {
        #pragma unroll
        for (int j = 0; j < 4; j++)
            we[j] = *(const float4*)(wext + (size_t)j * C + lane * 4);
    }

    for (int i = 0; i < 16; i++) {
        int r = wid * 16 + i;
        float4 v = *(float4*)(Csm + (size_t)r * LDC + lane * 4);
        if (EPI == 1) {
            int dd = s_dst[r];
            if (dd >= 0)
                red4(out + (size_t)dd * C + lane * 4, v.x, v.y, v.z, v.w);
            continue;
        }
        int row = row0 + r;
        if (row >= nrows) continue;

        if (EPI == 0) {
            *(float4*)(out + (size_t)row * C + lane * 4) = v;
            continue;
        }
        if (EPI == 3) {   // meta extras: rank-4 update before GN
            float t0 = turn[2 * row], t1 = turn[2 * row + 1];
            float cc0 = control[row], it = inter[row];
            v.x += t0 * we[0].x + t1 * we[1].x + cc0 * we[2].x + it * we[3].x;
            v.y += t0 * we[0].y + t1 * we[1].y + cc0 * we[2].y + it * we[3].y;
            v.z += t0 * we[0].z + t1 * we[1].z + cc0 * we[2].z + it * we[3].z;
            v.w += t0 * we[0].w + t1 * we[1].w + cc0 * we[2].w + it * we[3].w;
        }
        // GroupNorm(1, C) over the row
        float s1 = v.x + v.y + v.z + v.w;
        float s2 = v.x * v.x + v.y * v.y + v.z * v.z + v.w * v.w;
        #pragma unroll
        for (int o = 16; o >= 1; o >>= 1) {
            s1 += __shfl_xor_sync(0xffffffffu, s1, o);
            s2 += __shfl_xor_sync(0xffffffffu, s2, o);
        }
        float mu = s1 * (1.f / 128.f);
        float var = s2 * (1.f / 128.f) - mu * mu;
        float rs = rsqrtf(var + 1e-5f);
        float v0 = (v.x - mu) * rs * gv.x + bv.x;
        float v1 = (v.y - mu) * rs * gv.y + bv.y;
        float v2 = (v.z - mu) * rs * gv.z + bv.z;
        float v3 = (v.w - mu) * rs * gv.w + bv.w;

        if (EPI == 4) {
            *(float4*)(out + (size_t)row * C + lane * 4) = make_float4(v0, v1, v2, v3);
            continue;
        }
        if (EPI == 2) {
            float4 rr = *(const float4*)(addb + (size_t)row * C + lane * 4);
            v0 += rr.x; v1 += rr.y; v2 += rr.z; v3 += rr.w;
        }
        v0 = fmaxf(v0, 0.f); v1 = fmaxf(v1, 0.f);
        v2 = fmaxf(v2, 0.f); v3 = fmaxf(v3, 0.f);
        *(float4*)(out + (size_t)row * C + lane * 4) = make_float4(v0, v1, v2, v3);
        // bf16 hi/lo split for the next GEMM
        __nv_bfloat16 h0 = __float2bfloat16(v0), h1 = __float2bfloat16(v1);
        __nv_bfloat16 h2 = __float2bfloat16(v2), h3 = __float2bfloat16(v3);
        __nv_bfloat162 hh0; hh0.x = h0; hh0.y = h1;
        __nv_bfloat162 hh1; hh1.x = h2; hh1.y = h3;
        uint2 H; H.x = *(u32*)&hh0; H.y = *(u32*)&hh1;
        uint2 L;
        L.x = pack_bf2(v0 - __bfloat162float(h0), v1 - __bfloat162float(h1));
        L.y = pack_bf2(v2 - __bfloat162float(h2), v3 - __bfloat162float(h3));
        *(uint2*)((char*)fo_hi + ((size_t)row * C + lane * 4) * 2) = H;
        *(uint2*)((char*)fo_lo + ((size_t)row * C + lane * 4) * 2) = L;
    }
}

// ================= small kernels =================
__global__ void wsplit_all(
    const float* __restrict__ w_in2, const float* __restrict__ w_seg2,
    const float* __restrict__ w_meta,
    const float* __restrict__ ctr_w, const float* __restrict__ pre_w,
    const float* __restrict__ suc_w, const float* __restrict__ left_w,
    const float* __restrict__ right_w, const float* __restrict__ ctr2_w,
    __nv_bfloat16* __restrict__ hi, __nv_bfloat16* __restrict__ lo)
{
    int idx = blockIdx.x * 256 + threadIdx.x;
    if (idx >= 67 * CC) return;
    int mat = idx >> 14;
    int rem = idx & 16383;
    int k = rem >> 7, n = rem & 127;
    const float* src;
    if      (mat == 0) src = w_in2 + rem;
    else if (mat == 1) src = w_seg2 + rem;
    else if (mat == 2) src = w_meta + rem;             // rows 0..127 of (132,C)
    else if (mat < 7)  src = ctr_w   + (size_t)(mat - 3) * CC + rem;
    else if (mat < 31) src = pre_w   + (size_t)(mat - 7) * CC + rem;
    else if (mat < 55) src = suc_w   + (size_t)(mat - 31) * CC + rem;
    else if (mat < 59) src = left_w  + (size_t)(mat - 55) * CC + rem;
    else if (mat < 63) src = right_w + (size_t)(mat - 59) * CC + rem;
    else               src = ctr2_w  + (size_t)(mat - 63) * CC + rem;
    float x = *src;
    __nv_bfloat16 h = __float2bfloat16(x);
    size_t o = (size_t)mat * CC + (size_t)n * C + k;   // transposed Wt[n][k]
    hi[o] = h;
    lo[o] = __float2bfloat16(x - __bfloat162float(h));
}

__global__ void ew_in_split(
    const float* __restrict__ ctrs, const float* __restrict__ feats,
    const float* __restrict__ w_in1, const float* __restrict__ b_in1,
    const float* __restrict__ w_seg1, const float* __restrict__ b_seg1,
    __nv_bfloat16* __restrict__ h1h, __nv_bfloat16* __restrict__ h1l,
    __nv_bfloat16* __restrict__ h2h, __nv_bfloat16* __restrict__ h2l)
{
    int i = blockIdx.x * 256 + threadIdx.x;
    if (i >= N_NODES * C) return;
    int n = i >> 7, cc = i & 127;
    float x0 = ctrs[2 * n], x1 = ctrs[2 * n + 1];
    float a = fmaxf(x0 * w_in1[cc] + x1 * w_in1[C + cc] + b_in1[cc], 0.f);
    __nv_bfloat16 ah = __float2bfloat16(a);
    h1h[i] = ah;
    h1l[i] = __float2bfloat16(a - __bfloat162float(ah));
    float y0 = feats[2 * n], y1 = feats[2 * n + 1];
    float b = fmaxf(y0 * w_seg1[cc] + y1 * w_seg1[C + cc] + b_seg1[cc], 0.f);
    __nv_bfloat16 bh = __float2bfloat16(b);
    h2h[i] = bh;
    h2l[i] = __float2bfloat16(b - __bfloat162float(bh));
}

__global__ void ew_gnrelu_split(const float* __restrict__ T, const float* __restrict__ g,
                                const float* __restrict__ b,
                                __nv_bfloat16* __restrict__ Xhi,
                                __nv_bfloat16* __restrict__ Xlo)
{
    int n = blockIdx.x * 8 + (threadIdx.x >> 5);
    int lane = threadIdx.x & 31;
    if (n >= N_NODES) return;
    float4 v = *(const float4*)(T + (size_t)n * C + lane * 4);
    float s1 = v.x + v.y + v.z + v.w;
    float s2 = v.x * v.x + v.y * v.y + v.z * v.z + v.w * v.w;
    #pragma unroll
    for (int o = 16; o >= 1; o >>= 1) {
        s1 += __shfl_xor_sync(0xffffffffu, s1, o);
        s2 += __shfl_xor_sync(0xffffffffu, s2, o);
    }
    float mu = s1 * (1.f / 128.f);
    float var = s2 * (1.f / 128.f) - mu * mu;
    float sc = rsqrtf(var + 1e-5f);
    float4 gv = *(const float4*)(g + lane * 4);
    float4 bv = *(const float4*)(b + lane * 4);
    float v0 = fmaxf((v.x - mu) * sc * gv.x + bv.x, 0.f);
    float v1 = fmaxf((v.y - mu) * sc * gv.y + bv.y, 0.f);
    float v2 = fmaxf((v.z - mu) * sc * gv.z + bv.z, 0.f);
    float v3 = fmaxf((v.w - mu) * sc * gv.w + bv.w, 0.f);
    __nv_bfloat16 h0 = __float2bfloat16(v0), h1 = __float2bfloat16(v1);
    __nv_bfloat16 h2 = __float2bfloat16(v2), h3 = __float2bfloat16(v3);
    __nv_bfloat162 hh0; hh0.x = h0; hh0.y = h1;
    __nv_bfloat162 hh1; hh1.x = h2; hh1.y = h3;
    uint2 H; H.x = *(u32*)&hh0; H.y = *(u32*)&hh1;
    uint2 L;
    L.x = pack_bf2(v0 - __bfloat162float(h0), v1 - __bfloat162float(h1));
    L.y = pack_bf2(v2 - __bfloat162float(h2), v3 - __bfloat162float(h3));
    size_t off = (size_t)n * 32 + lane;
    ((uint2*)Xhi)[off] = H;
    ((uint2*)Xlo)[off] = L;
}

__global__ void ew_copy(const float* __restrict__ src, float* __restrict__ dst, int n) {
    int i = blockIdx.x * 256 + threadIdx.x;
    if (i < n) dst[i] = src[i];
}

// ================= host launcher =================
extern "C" void kernel_launch(void* const* d_in, const int* in_sizes, int n_in,
                              void* d_out, int out_size)
{
    const float* control  = (const float*)d_in[0];
    const float* turn     = (const float*)d_in[1];
    const float* inter    = (const float*)d_in[2];
    const float* ctrs     = (const float*)d_in[3];
    const float* feats    = (const float*)d_in[4];
    const int*   pre      = (const int*)d_in[5];
    const int*   suc      = (const int*)d_in[6];
    const int*   left     = (const int*)d_in[7];
    const int*   right    = (const int*)d_in[8];
    const float* w_in1    = (const float*)d_in[9];
    const float* b_in1    = (const float*)d_in[10];
    const float* w_in2    = (const float*)d_in[11];
    const float* gn_in_g  = (const float*)d_in[12];
    const float* gn_in_b  = (const float*)d_in[13];
    const float* w_seg1   = (const float*)d_in[14];
    const float* b_seg1   = (const float*)d_in[15];
    const float* w_seg2   = (const float*)d_in[16];
    const float* gn_seg_g = (const float*)d_in[17];
    const float* gn_seg_b = (const float*)d_in[18];
    const float* w_meta   = (const float*)d_in[19];
    const float* gn_m_g   = (const float*)d_in[20];
    const float* gn_m_b   = (const float*)d_in[21];
    const float* ctr_w    = (const float*)d_in[22];
    const float* pre_w    = (const float*)d_in[23];
    const float* suc_w    = (const float*)d_in[24];
    const float* left_w   = (const float*)d_in[25];
    const float* right_w  = (const float*)d_in[26];
    const float* norm_g   = (const float*)d_in[27];
    const float* norm_b   = (const float*)d_in[28];
    const float* ctr2_w   = (const float*)d_in[29];
    const float* ctr2_g   = (const float*)d_in[30];
    const float* ctr2_b   = (const float*)d_in[31];

    float *F, *G, *T;
    __nv_bfloat16 *Fhi, *Flo, *Xhi, *Xlo, *Whi, *Wlo;
    cudaGetSymbolAddress((void**)&F, g_F);
    cudaGetSymbolAddress((void**)&G, g_G);
    cudaGetSymbolAddress((void**)&T, g_T);
    cudaGetSymbolAddress((void**)&Fhi, g_Fhi);
    cudaGetSymbolAddress((void**)&Flo, g_Flo);
    cudaGetSymbolAddress((void**)&Xhi, g_Xhi);
    cudaGetSymbolAddress((void**)&Xlo, g_Xlo);
    cudaGetSymbolAddress((void**)&Whi, g_Whi);
    cudaGetSymbolAddress((void**)&Wlo, g_Wlo);

    cudaFuncSetAttribute(hmma_gemm<0,0>, cudaFuncAttributeMaxDynamicSharedMemorySize, DSM);
    cudaFuncSetAttribute(hmma_gemm<1,1>, cudaFuncAttributeMaxDynamicSharedMemorySize, DSM);
    cudaFuncSetAttribute(hmma_gemm<0,2>, cudaFuncAttributeMaxDynamicSharedMemorySize, DSM);
    cudaFuncSetAttribute(hmma_gemm<0,3>, cudaFuncAttributeMaxDynamicSharedMemorySize, DSM);
    cudaFuncSetAttribute(hmma_gemm<0,4>, cudaFuncAttributeMaxDynamicSharedMemorySize, DSM);

    const int NB  = (N_NODES + 127) / 128;
    const int NBP = (EP + 127) / 128;
    const int NBL = (EL + 127) / 128;
    const float* wext = w_meta + 128 * C;   // rows 128..131 of (132, C)

    // launch 1: all weight splits (transposed)
    wsplit_all<<<(67 * CC + 255) / 256, 256>>>(w_in2, w_seg2, w_meta,
                                               ctr_w, pre_w, suc_w, left_w, right_w,
                                               ctr2_w, Whi, Wlo);
    // launch 2: first linear+relu for both branches, split to bf16
    ew_in_split<<<(N_NODES * C + 255) / 256, 256>>>(ctrs, feats, w_in1, b_in1,
                                                    w_seg1, b_seg1, Xhi, Xlo, Fhi, Flo);
    // launch 3: T = gn(H1 @ w_in2)            (EPI4)
    hmma_gemm<0,4><<<NB, 256, DSM>>>(Xhi, Xlo, Whi + OFF_IN2, Wlo + OFF_IN2, 0,
        T, gn_in_g, gn_in_b, nullptr, nullptr, nullptr, nullptr, nullptr, 0, N_NODES,
        nullptr, nullptr, nullptr, nullptr);
    // launch 4: F = relu(gn(H2 @ w_seg2) + T), split -> Xhi/Xlo   (EPI2)
    hmma_gemm<0,2><<<NB, 256, DSM>>>(Fhi, Flo, Whi + OFF_SEG2, Wlo + OFF_SEG2, 0,
        F, gn_seg_g, gn_seg_b, T, Xhi, Xlo, nullptr, nullptr, 0, N_NODES,
        nullptr, nullptr, nullptr, nullptr);
    // launch 5: F = relu(gn(feat @ w_meta128 + extras @ wext)), split -> Fhi/Flo (EPI3)
    hmma_gemm<0,3><<<NB, 256, DSM>>>(Xhi, Xlo, Whi + OFF_META, Wlo + OFF_META, 0,
        F, gn_m_g, gn_m_b, nullptr, Fhi, Flo, nullptr, nullptr, 0, N_NODES,
        turn, control, inter, wext);

    // ---- 4 fuse layers ----  (launch 6 = layer-0 ctr -> ncu capture target)
    for (int i = 0; i < 4; i++) {
        float* Fi = (i & 1) ? G : F;
        float* Fo = (i == 3) ? (float*)d_out : ((i & 1) ? F : G);

        hmma_gemm<0,0><<<NB, 256, DSM>>>(
            Fhi, Flo, Whi + OFF_CTR + (size_t)i * CC, Wlo + OFF_CTR + (size_t)i * CC, 0,
            T, nullptr, nullptr, nullptr, nullptr, nullptr, nullptr, nullptr, 0, N_NODES,
            nullptr, nullptr, nullptr, nullptr);
        hmma_gemm<1,1><<<dim3(NBP, S), 256, DSM>>>(
            Fhi, Flo, Whi + OFF_PRE + (size_t)i * S * CC, Wlo + OFF_PRE + (size_t)i * S * CC, CC,
            T, nullptr, nullptr, nullptr, nullptr, nullptr, pre, pre + EP, 2LL * EP, EP,
            nullptr, nullptr, nullptr, nullptr);
        hmma_gemm<1,1><<<dim3(NBP, S), 256, DSM>>>(
            Fhi, Flo, Whi + OFF_SUC + (size_t)i * S * CC, Wlo + OFF_SUC + (size_t)i * S * CC, CC,
            T, nullptr, nullptr, nullptr, nullptr, nullptr, suc, suc + EP, 2LL * EP, EP,
            nullptr, nullptr, nullptr, nullptr);
        hmma_gemm<1,1><<<NBL, 256, DSM>>>(
            Fhi, Flo, Whi + OFF_LEFT + (size_t)i * CC, Wlo + OFF_LEFT + (size_t)i * CC, 0,
            T, nullptr, nullptr, nullptr, nullptr, nullptr, left, left + EL, 0, EL,
            nullptr, nullptr, nullptr, nullptr);
        hmma_gemm<1,1><<<NBL, 256, DSM>>>(
            Fhi, Flo, Whi + OFF_RIGHT + (size_t)i * CC, Wlo + OFF_RIGHT + (size_t)i * CC, 0,
            T, nullptr, nullptr, nullptr, nullptr, nullptr, right, right + EL, 0, EL,
            nullptr, nullptr, nullptr, nullptr);
        ew_gnrelu_split<<<(N_NODES + 7) / 8, 256>>>(T, norm_g + (size_t)i * C,
                                                    norm_b + (size_t)i * C, Xhi, Xlo);
        hmma_gemm<0,2><<<NB, 256, DSM>>>(
            Xhi, Xlo, Whi + OFF_CTR2 + (size_t)i * CC, Wlo + OFF_CTR2 + (size_t)i * CC, 0,
            Fo, ctr2_g + (size_t)i * C, ctr2_b + (size_t)i * C, Fi, Fhi, Flo,
            nullptr, nullptr, 0, N_NODES,
            nullptr, nullptr, nullptr, nullptr);
    }

    ew_copy<<<(N_NODES * 2 + 255) / 256, 256>>>(ctrs, (float*)d_out + (size_t)N_NODES * C,
                                                N_NODES * 2);
}

// round 6
// speedup vs baseline: 2.5025x; 1.1203x over previous
#include <cuda_runtime.h>
#include <cuda_bf16.h>
#include <cstdint>
#include <cstddef>

#define N_NODES 200000
#define C 128
#define S 6
#define EP 100000
#define EL 25000
#define CC 16384

typedef unsigned long long u64;
typedef unsigned int u32;

// ---- static device scratch ----
__device__ float g_F[(size_t)N_NODES * C];
__device__ float g_G[(size_t)N_NODES * C];
__device__ float g_T[(size_t)N_NODES * C];
__device__ __nv_bfloat16 g_Fhi[(size_t)N_NODES * C];
__device__ __nv_bfloat16 g_Flo[(size_t)N_NODES * C];
__device__ __nv_bfloat16 g_Xhi[(size_t)N_NODES * C];
__device__ __nv_bfloat16 g_Xlo[(size_t)N_NODES * C];
__device__ __nv_bfloat16 g_Whi[(size_t)67 * CC];
__device__ __nv_bfloat16 g_Wlo[(size_t)67 * CC];

// weight slots (transposed Wt[n][k], bf16 hi/lo)
#define OFF_IN2   0
#define OFF_SEG2  (1 * CC)
#define OFF_META  (2 * CC)
#define OFF_CTR   (3 * CC)
#define OFF_PRE   (7 * CC)
#define OFF_SUC   (31 * CC)
#define OFF_LEFT  (55 * CC)
#define OFF_RIGHT (59 * CC)
#define OFF_CTR2  (63 * CC)

// ---- helpers ----
__device__ __forceinline__ u32 cvta_sm(const void* p) {
    u32 a;
    asm("{ .reg .u64 t; cvta.to.shared.u64 t, %1; cvt.u32.u64 %0, t; }" : "=r"(a) : "l"(p));
    return a;
}
__device__ __forceinline__ void red4(float* p, float a, float b, float c, float d) {
    asm volatile("red.global.add.v4.f32 [%0], {%1,%2,%3,%4};"
                 :: "l"(p), "f"(a), "f"(b), "f"(c), "f"(d) : "memory");
}
__device__ __forceinline__ u32 pack_bf2(float a, float b) {
    __nv_bfloat162 t = __floats2bfloat162_rn(a, b);
    return *(u32*)&t;
}
__device__ __forceinline__ void ldm4(u32* r, u32 addr) {
    asm volatile("ldmatrix.sync.aligned.m8n8.x4.shared.b16 {%0,%1,%2,%3}, [%4];"
                 : "=r"(r[0]), "=r"(r[1]), "=r"(r[2]), "=r"(r[3]) : "r"(addr));
}
__device__ __forceinline__ void mma_bf16(float* c, const u32* a, const u32* b) {
    asm volatile(
        "mma.sync.aligned.m16n8k16.row.col.f32.bf16.bf16.f32 "
        "{%0,%1,%2,%3}, {%4,%5,%6,%7}, {%8,%9}, {%0,%1,%2,%3};"
        : "+f"(c[0]), "+f"(c[1]), "+f"(c[2]), "+f"(c[3])
        : "r"(a[0]), "r"(a[1]), "r"(a[2]), "r"(a[3]), "r"(b[0]), "r"(b[1]));
}
__device__ __forceinline__ void cpa16(u32 dst, const void* src, u32 sz) {
    asm volatile("cp.async.cg.shared.global [%0], [%1], 16, %2;"
                 :: "r"(dst), "l"(src), "r"(sz) : "memory");
}
#define CP_COMMIT() asm volatile("cp.async.commit_group;" ::: "memory")

// ---- hmma smem layout: swizzled 64B rows, 3 quarter-buffers ----
// matrix tile: 128 rows x 64B (32 bf16). chunk swizzle: c' = c ^ ((r>>1)&3)
#define MTB   8192               // one matrix tile bytes
#define OFF_AH 0
#define OFF_AL (1 * MTB)
#define OFF_BH (2 * MTB)
#define OFF_BL (3 * MTB)
#define QSET  (4 * MTB)          // 32768
#define SM_IDX (3 * QSET)        // 98304: dst[128], src[128]
#define DSM   (SM_IDX + 1024)    // 99328
#define LDC   132                // floats per row of smem C tile

__device__ __forceinline__ u32 swz(int r, int c) {
    return (u32)r * 64u + (u32)((c ^ ((r >> 1) & 3)) << 4);
}

template<int GATHER>
__device__ __forceinline__ void stage_q(
    u32 smb, int q, int bi, int tid, int row0, int nrows, const int* s_src,
    const __nv_bfloat16* Ahi, const __nv_bfloat16* Alo,
    const __nv_bfloat16* WH, const __nv_bfloat16* WL)
{
    u32 bbase = smb + (u32)bi * QSET;
    #pragma unroll
    for (int j = 0; j < 2; j++) {
        int id = tid + j * 256;       // 0..511
        int r = id >> 2, sg = id & 3;
        u32 doff = swz(r, sg);
        u32 asz = 16;
        long long arow;
        if (GATHER) {
            arow = s_src[r];
        } else {
            int gr = row0 + r;
            if (gr >= nrows) { asz = 0; gr = 0; }
            arow = gr;
        }
        size_t abyte = (size_t)arow * 256 + (size_t)q * 64 + (size_t)sg * 16;
        cpa16(bbase + OFF_AH + doff, (const char*)Ahi + abyte, asz);
        cpa16(bbase + OFF_AL + doff, (const char*)Alo + abyte, asz);
        size_t wbyte = (size_t)r * 256 + (size_t)q * 64 + (size_t)sg * 16;
        cpa16(bbase + OFF_BH + doff, (const char*)WH + wbyte, 16);
        cpa16(bbase + OFF_BL + doff, (const char*)WL + wbyte, 16);
    }
    CP_COMMIT();
}

// ================= bf16x3 mma.sync GEMM, 3-buffer cp.async pipeline =============
// EPI: 0 store | 1 RED scatter | 2 GN+add+relu+split | 3 extras+GN+relu+split | 4 GN only
template<int GATHER, int EPI>
__global__ __launch_bounds__(256, 2) void hmma_gemm(
    const __nv_bfloat16* __restrict__ Ahi, const __nv_bfloat16* __restrict__ Alo,
    const __nv_bfloat16* __restrict__ Whi, const __nv_bfloat16* __restrict__ Wlo,
    long long wstride,
    float* __restrict__ out,
    const float* __restrict__ gng, const float* __restrict__ gnb,
    const float* __restrict__ addb,
    __nv_bfloat16* __restrict__ fo_hi, __nv_bfloat16* __restrict__ fo_lo,
    const int* __restrict__ dst_base, const int* __restrict__ src_base,
    long long istride, int nrows,
    const float* __restrict__ turn, const float* __restrict__ control,
    const float* __restrict__ inter, const float* __restrict__ wext)
{
    extern __shared__ char dsm[];
    const int tid = threadIdx.x;
    const int wid = tid >> 5;
    const int lane = tid & 31;
    const int row0 = blockIdx.x * 128;
    const u32 smb = cvta_sm(dsm);

    int* s_dst = (int*)(dsm + SM_IDX);
    int* s_src = s_dst + 128;
    if (GATHER) {
        if (tid < 128) {
            int e = row0 + tid;
            const int* dp = dst_base + blockIdx.y * istride;
            const int* sp = src_base + blockIdx.y * istride;
            s_dst[tid] = (e < nrows) ? dp[e] : -1;
            s_src[tid] = (e < nrows) ? sp[e] : 0;
        }
        __syncthreads();
    }

    const __nv_bfloat16* WH = Whi + (long long)blockIdx.y * wstride;
    const __nv_bfloat16* WL = Wlo + (long long)blockIdx.y * wstride;

    const int wm = (wid & 3) * 32;
    const int wn = (wid >> 2) * 64;

    float acc[2][8][4];
    #pragma unroll
    for (int mi = 0; mi < 2; mi++)
        #pragma unroll
        for (int nj = 0; nj < 8; nj++)
            #pragma unroll
            for (int q = 0; q < 4; q++) acc[mi][nj][q] = 0.f;

    // per-thread ldmatrix row geometry (rows fixed; chunk varies with ks)
    const int ra = wm + (lane & 15);              // A rows ra, ra+16 (same xor mask)
    const u32 xa = (u32)((ra >> 1) & 3);
    const int ca = lane >> 4;                     // 0/1
    const int rb = wn + (lane & 7) + ((lane >> 4) & 1) * 8;  // B rows rb + ni*16
    const u32 xb = (u32)((rb >> 1) & 3);
    const int cb = (lane >> 3) & 1;

    stage_q<GATHER>(smb, 0, 0, tid, row0, nrows, s_src, Ahi, Alo, WH, WL);
    stage_q<GATHER>(smb, 1, 1, tid, row0, nrows, s_src, Ahi, Alo, WH, WL);
    stage_q<GATHER>(smb, 2, 2, tid, row0, nrows, s_src, Ahi, Alo, WH, WL);

#define MMAS(A, B) do {                                                        \
    _Pragma("unroll") for (int mi = 0; mi < 2; mi++)                           \
        _Pragma("unroll") for (int ni = 0; ni < 4; ni++) {                     \
            mma_bf16(acc[mi][2 * ni],     (A)[mi], &(B)[ni][0]);               \
            mma_bf16(acc[mi][2 * ni + 1], (A)[mi], &(B)[ni][2]);               \
        }                                                                      \
} while (0)

    #pragma unroll
    for (int q = 0; q < 4; q++) {
        if (q == 0)      asm volatile("cp.async.wait_group 2;" ::: "memory");
        else if (q == 1) asm volatile("cp.async.wait_group 2;" ::: "memory");
        else if (q == 2) asm volatile("cp.async.wait_group 1;" ::: "memory");
        else             asm volatile("cp.async.wait_group 0;" ::: "memory");
        __syncthreads();

        const u32 qb = smb + (u32)(q % 3) * QSET;
        #pragma unroll
        for (int ks = 0; ks < 2; ks++) {
            const u32 ach = (u32)(ks * 2 + ca) ^ xa;
            const u32 bch = (u32)(ks * 2 + cb) ^ xb;
            const u32 aoff = (u32)ra * 64u + (ach << 4);
            u32 a0[2][4], a1[2][4], b0[4][4], b1[4][4];
            ldm4(a0[0], qb + OFF_AH + aoff);
            ldm4(a0[1], qb + OFF_AH + aoff + 16 * 64);
            #pragma unroll
            for (int ni = 0; ni < 4; ni++)
                ldm4(b0[ni], qb + OFF_BH + (u32)(rb + ni * 16) * 64u + (bch << 4));
            MMAS(a0, b0);                       // Ah*Bh
            ldm4(a1[0], qb + OFF_AL + aoff);
            ldm4(a1[1], qb + OFF_AL + aoff + 16 * 64);
            MMAS(a1, b0);                       // Al*Bh
            #pragma unroll
            for (int ni = 0; ni < 4; ni++)
                ldm4(b1[ni], qb + OFF_BL + (u32)(rb + ni * 16) * 64u + (bch << 4));
            MMAS(a0, b1);                       // Ah*Bl
        }

        if (q == 0) {
            __syncthreads();   // all warps done reading buf0 before restage
            stage_q<GATHER>(smb, 3, 0, tid, row0, nrows, s_src, Ahi, Alo, WH, WL);
        }
    }
#undef MMAS

    // ---- accumulators -> smem C tile ----
    __syncthreads();
    float* Csm = (float*)dsm;
    #pragma unroll
    for (int mi = 0; mi < 2; mi++)
        #pragma unroll
        for (int nj = 0; nj < 8; nj++) {
            int r = wm + mi * 16 + (lane >> 2);
            int c = wn + nj * 8 + (lane & 3) * 2;
            float* p = Csm + (size_t)r * LDC + c;
            p[0] = acc[mi][nj][0];
            p[1] = acc[mi][nj][1];
            p[8 * LDC] = acc[mi][nj][2];
            p[8 * LDC + 1] = acc[mi][nj][3];
        }
    __syncthreads();

    // ---- row-wise epilogue: each warp owns 16 full rows ----
    float4 gv, bv;
    float4 we[4];
    if (EPI == 2 || EPI == 3 || EPI == 4) {
        gv = *(const float4*)(gng + lane * 4);
        bv = *(const float4*)(gnb + lane * 4);
    }
    if (EPI == 3) {
        #pragma unroll
        for (int j = 0; j < 4; j++)
            we[j] = *(const float4*)(wext + (size_t)j * C + lane * 4);
    }

    for (int i = 0; i < 16; i++) {
        int r = wid * 16 + i;
        float4 v = *(float4*)(Csm + (size_t)r * LDC + lane * 4);
        if (EPI == 1) {
            int dd = s_dst[r];
            if (dd >= 0)
                red4(out + (size_t)dd * C + lane * 4, v.x, v.y, v.z, v.w);
            continue;
        }
        int row = row0 + r;
        if (row >= nrows) continue;

        if (EPI == 0) {
            *(float4*)(out + (size_t)row * C + lane * 4) = v;
            continue;
        }
        if (EPI == 3) {   // meta extras: rank-4 update before GN
            float t0 = turn[2 * row], t1 = turn[2 * row + 1];
            float cc0 = control[row], it = inter[row];
            v.x += t0 * we[0].x + t1 * we[1].x + cc0 * we[2].x + it * we[3].x;
            v.y += t0 * we[0].y + t1 * we[1].y + cc0 * we[2].y + it * we[3].y;
            v.z += t0 * we[0].z + t1 * we[1].z + cc0 * we[2].z + it * we[3].z;
            v.w += t0 * we[0].w + t1 * we[1].w + cc0 * we[2].w + it * we[3].w;
        }
        // GroupNorm(1, C) over the row
        float s1 = v.x + v.y + v.z + v.w;
        float s2 = v.x * v.x + v.y * v.y + v.z * v.z + v.w * v.w;
        #pragma unroll
        for (int o = 16; o >= 1; o >>= 1) {
            s1 += __shfl_xor_sync(0xffffffffu, s1, o);
            s2 += __shfl_xor_sync(0xffffffffu, s2, o);
        }
        float mu = s1 * (1.f / 128.f);
        float var = s2 * (1.f / 128.f) - mu * mu;
        float rs = rsqrtf(var + 1e-5f);
        float v0 = (v.x - mu) * rs * gv.x + bv.x;
        float v1 = (v.y - mu) * rs * gv.y + bv.y;
        float v2 = (v.z - mu) * rs * gv.z + bv.z;
        float v3 = (v.w - mu) * rs * gv.w + bv.w;

        if (EPI == 4) {
            *(float4*)(out + (size_t)row * C + lane * 4) = make_float4(v0, v1, v2, v3);
            continue;
        }
        if (EPI == 2) {
            float4 rr = *(const float4*)(addb + (size_t)row * C + lane * 4);
            v0 += rr.x; v1 += rr.y; v2 += rr.z; v3 += rr.w;
        }
        v0 = fmaxf(v0, 0.f); v1 = fmaxf(v1, 0.f);
        v2 = fmaxf(v2, 0.f); v3 = fmaxf(v3, 0.f);
        *(float4*)(out + (size_t)row * C + lane * 4) = make_float4(v0, v1, v2, v3);
        // bf16 hi/lo split for the next GEMM
        __nv_bfloat16 h0 = __float2bfloat16(v0), h1 = __float2bfloat16(v1);
        __nv_bfloat16 h2 = __float2bfloat16(v2), h3 = __float2bfloat16(v3);
        __nv_bfloat162 hh0; hh0.x = h0; hh0.y = h1;
        __nv_bfloat162 hh1; hh1.x = h2; hh1.y = h3;
        uint2 H; H.x = *(u32*)&hh0; H.y = *(u32*)&hh1;
        uint2 L;
        L.x = pack_bf2(v0 - __bfloat162float(h0), v1 - __bfloat162float(h1));
        L.y = pack_bf2(v2 - __bfloat162float(h2), v3 - __bfloat162float(h3));
        *(uint2*)((char*)fo_hi + ((size_t)row * C + lane * 4) * 2) = H;
        *(uint2*)((char*)fo_lo + ((size_t)row * C + lane * 4) * 2) = L;
    }
}

// ================= small kernels =================
__global__ void wsplit_all(
    const float* __restrict__ w_in2, const float* __restrict__ w_seg2,
    const float* __restrict__ w_meta,
    const float* __restrict__ ctr_w, const float* __restrict__ pre_w,
    const float* __restrict__ suc_w, const float* __restrict__ left_w,
    const float* __restrict__ right_w, const float* __restrict__ ctr2_w,
    __nv_bfloat16* __restrict__ hi, __nv_bfloat16* __restrict__ lo)
{
    int idx = blockIdx.x * 256 + threadIdx.x;
    if (idx >= 67 * CC) return;
    int mat = idx >> 14;
    int rem = idx & 16383;
    int k = rem >> 7, n = rem & 127;
    const float* src;
    if      (mat == 0) src = w_in2 + rem;
    else if (mat == 1) src = w_seg2 + rem;
    else if (mat == 2) src = w_meta + rem;             // rows 0..127 of (132,C)
    else if (mat < 7)  src = ctr_w   + (size_t)(mat - 3) * CC + rem;
    else if (mat < 31) src = pre_w   + (size_t)(mat - 7) * CC + rem;
    else if (mat < 55) src = suc_w   + (size_t)(mat - 31) * CC + rem;
    else if (mat < 59) src = left_w  + (size_t)(mat - 55) * CC + rem;
    else if (mat < 63) src = right_w + (size_t)(mat - 59) * CC + rem;
    else               src = ctr2_w  + (size_t)(mat - 63) * CC + rem;
    float x = *src;
    __nv_bfloat16 h = __float2bfloat16(x);
    size_t o = (size_t)mat * CC + (size_t)n * C + k;   // transposed Wt[n][k]
    hi[o] = h;
    lo[o] = __float2bfloat16(x - __bfloat162float(h));
}

__global__ void ew_in_split(
    const float* __restrict__ ctrs, const float* __restrict__ feats,
    const float* __restrict__ w_in1, const float* __restrict__ b_in1,
    const float* __restrict__ w_seg1, const float* __restrict__ b_seg1,
    __nv_bfloat16* __restrict__ h1h, __nv_bfloat16* __restrict__ h1l,
    __nv_bfloat16* __restrict__ h2h, __nv_bfloat16* __restrict__ h2l)
{
    int i = blockIdx.x * 256 + threadIdx.x;
    if (i >= N_NODES * C) return;
    int n = i >> 7, cc = i & 127;
    float x0 = ctrs[2 * n], x1 = ctrs[2 * n + 1];
    float a = fmaxf(x0 * w_in1[cc] + x1 * w_in1[C + cc] + b_in1[cc], 0.f);
    __nv_bfloat16 ah = __float2bfloat16(a);
    h1h[i] = ah;
    h1l[i] = __float2bfloat16(a - __bfloat162float(ah));
    float y0 = feats[2 * n], y1 = feats[2 * n + 1];
    float b = fmaxf(y0 * w_seg1[cc] + y1 * w_seg1[C + cc] + b_seg1[cc], 0.f);
    __nv_bfloat16 bh = __float2bfloat16(b);
    h2h[i] = bh;
    h2l[i] = __float2bfloat16(b - __bfloat162float(bh));
}

__global__ void ew_gnrelu_split(const float* __restrict__ T, const float* __restrict__ g,
                                const float* __restrict__ b,
                                __nv_bfloat16* __restrict__ Xhi,
                                __nv_bfloat16* __restrict__ Xlo)
{
    int n = blockIdx.x * 8 + (threadIdx.x >> 5);
    int lane = threadIdx.x & 31;
    if (n >= N_NODES) return;
    float4 v = *(const float4*)(T + (size_t)n * C + lane * 4);
    float s1 = v.x + v.y + v.z + v.w;
    float s2 = v.x * v.x + v.y * v.y + v.z * v.z + v.w * v.w;
    #pragma unroll
    for (int o = 16; o >= 1; o >>= 1) {
        s1 += __shfl_xor_sync(0xffffffffu, s1, o);
        s2 += __shfl_xor_sync(0xffffffffu, s2, o);
    }
    float mu = s1 * (1.f / 128.f);
    float var = s2 * (1.f / 128.f) - mu * mu;
    float sc = rsqrtf(var + 1e-5f);
    float4 gv = *(const float4*)(g + lane * 4);
    float4 bv = *(const float4*)(b + lane * 4);
    float v0 = fmaxf((v.x - mu) * sc * gv.x + bv.x, 0.f);
    float v1 = fmaxf((v.y - mu) * sc * gv.y + bv.y, 0.f);
    float v2 = fmaxf((v.z - mu) * sc * gv.z + bv.z, 0.f);
    float v3 = fmaxf((v.w - mu) * sc * gv.w + bv.w, 0.f);
    __nv_bfloat16 h0 = __float2bfloat16(v0), h1 = __float2bfloat16(v1);
    __nv_bfloat16 h2 = __float2bfloat16(v2), h3 = __float2bfloat16(v3);
    __nv_bfloat162 hh0; hh0.x = h0; hh0.y = h1;
    __nv_bfloat162 hh1; hh1.x = h2; hh1.y = h3;
    uint2 H; H.x = *(u32*)&hh0; H.y = *(u32*)&hh1;
    uint2 L;
    L.x = pack_bf2(v0 - __bfloat162float(h0), v1 - __bfloat162float(h1));
    L.y = pack_bf2(v2 - __bfloat162float(h2), v3 - __bfloat162float(h3));
    size_t off = (size_t)n * 32 + lane;
    ((uint2*)Xhi)[off] = H;
    ((uint2*)Xlo)[off] = L;
}

__global__ void ew_copy(const float* __restrict__ src, float* __restrict__ dst, int n) {
    int i = blockIdx.x * 256 + threadIdx.x;
    if (i < n) dst[i] = src[i];
}

// ================= host launcher =================
extern "C" void kernel_launch(void* const* d_in, const int* in_sizes, int n_in,
                              void* d_out, int out_size)
{
    const float* control  = (const float*)d_in[0];
    const float* turn     = (const float*)d_in[1];
    const float* inter    = (const float*)d_in[2];
    const float* ctrs     = (const float*)d_in[3];
    const float* feats    = (const float*)d_in[4];
    const int*   pre      = (const int*)d_in[5];
    const int*   suc      = (const int*)d_in[6];
    const int*   left     = (const int*)d_in[7];
    const int*   right    = (const int*)d_in[8];
    const float* w_in1    = (const float*)d_in[9];
    const float* b_in1    = (const float*)d_in[10];
    const float* w_in2    = (const float*)d_in[11];
    const float* gn_in_g  = (const float*)d_in[12];
    const float* gn_in_b  = (const float*)d_in[13];
    const float* w_seg1   = (const float*)d_in[14];
    const float* b_seg1   = (const float*)d_in[15];
    const float* w_seg2   = (const float*)d_in[16];
    const float* gn_seg_g = (const float*)d_in[17];
    const float* gn_seg_b = (const float*)d_in[18];
    const float* w_meta   = (const float*)d_in[19];
    const float* gn_m_g   = (const float*)d_in[20];
    const float* gn_m_b   = (const float*)d_in[21];
    const float* ctr_w    = (const float*)d_in[22];
    const float* pre_w    = (const float*)d_in[23];
    const float* suc_w    = (const float*)d_in[24];
    const float* left_w   = (const float*)d_in[25];
    const float* right_w  = (const float*)d_in[26];
    const float* norm_g   = (const float*)d_in[27];
    const float* norm_b   = (const float*)d_in[28];
    const float* ctr2_w   = (const float*)d_in[29];
    const float* ctr2_g   = (const float*)d_in[30];
    const float* ctr2_b   = (const float*)d_in[31];

    float *F, *G, *T;
    __nv_bfloat16 *Fhi, *Flo, *Xhi, *Xlo, *Whi, *Wlo;
    cudaGetSymbolAddress((void**)&F, g_F);
    cudaGetSymbolAddress((void**)&G, g_G);
    cudaGetSymbolAddress((void**)&T, g_T);
    cudaGetSymbolAddress((void**)&Fhi, g_Fhi);
    cudaGetSymbolAddress((void**)&Flo, g_Flo);
    cudaGetSymbolAddress((void**)&Xhi, g_Xhi);
    cudaGetSymbolAddress((void**)&Xlo, g_Xlo);
    cudaGetSymbolAddress((void**)&Whi, g_Whi);
    cudaGetSymbolAddress((void**)&Wlo, g_Wlo);

    cudaFuncSetAttribute(hmma_gemm<0,0>, cudaFuncAttributeMaxDynamicSharedMemorySize, DSM);
    cudaFuncSetAttribute(hmma_gemm<1,1>, cudaFuncAttributeMaxDynamicSharedMemorySize, DSM);
    cudaFuncSetAttribute(hmma_gemm<0,2>, cudaFuncAttributeMaxDynamicSharedMemorySize, DSM);
    cudaFuncSetAttribute(hmma_gemm<0,3>, cudaFuncAttributeMaxDynamicSharedMemorySize, DSM);
    cudaFuncSetAttribute(hmma_gemm<0,4>, cudaFuncAttributeMaxDynamicSharedMemorySize, DSM);

    const int NB  = (N_NODES + 127) / 128;
    const int NBP = (EP + 127) / 128;
    const int NBL = (EL + 127) / 128;
    const float* wext = w_meta + 128 * C;   // rows 128..131 of (132, C)

    // independent: output ctrs tail + weight split
    ew_copy<<<(N_NODES * 2 + 255) / 256, 256>>>(ctrs, (float*)d_out + (size_t)N_NODES * C,
                                                N_NODES * 2);
    wsplit_all<<<(67 * CC + 255) / 256, 256>>>(w_in2, w_seg2, w_meta,
                                               ctr_w, pre_w, suc_w, left_w, right_w,
                                               ctr2_w, Whi, Wlo);
    // first linear+relu for both branches, split to bf16
    ew_in_split<<<(N_NODES * C + 255) / 256, 256>>>(ctrs, feats, w_in1, b_in1,
                                                    w_seg1, b_seg1, Xhi, Xlo, Fhi, Flo);
    // T = gn(H1 @ w_in2)   (EPI4)
    hmma_gemm<0,4><<<NB, 256, DSM>>>(Xhi, Xlo, Whi + OFF_IN2, Wlo + OFF_IN2, 0,
        T, gn_in_g, gn_in_b, nullptr, nullptr, nullptr, nullptr, nullptr, 0, N_NODES,
        nullptr, nullptr, nullptr, nullptr);
    // F = relu(gn(H2 @ w_seg2) + T), split -> Xhi/Xlo   (EPI2)
    hmma_gemm<0,2><<<NB, 256, DSM>>>(Fhi, Flo, Whi + OFF_SEG2, Wlo + OFF_SEG2, 0,
        F, gn_seg_g, gn_seg_b, T, Xhi, Xlo, nullptr, nullptr, 0, N_NODES,
        nullptr, nullptr, nullptr, nullptr);
    // F = relu(gn(feat @ w_meta128 + extras @ wext)), split -> Fhi/Flo (EPI3)
    hmma_gemm<0,3><<<NB, 256, DSM>>>(Xhi, Xlo, Whi + OFF_META, Wlo + OFF_META, 0,
        F, gn_m_g, gn_m_b, nullptr, Fhi, Flo, nullptr, nullptr, 0, N_NODES,
        turn, control, inter, wext);

    // ---- 4 fuse layers ----
    for (int i = 0; i < 4; i++) {
        float* Fi = (i & 1) ? G : F;
        float* Fo = (i == 3) ? (float*)d_out : ((i & 1) ? F : G);

        hmma_gemm<0,0><<<NB, 256, DSM>>>(
            Fhi, Flo, Whi + OFF_CTR + (size_t)i * CC, Wlo + OFF_CTR + (size_t)i * CC, 0,
            T, nullptr, nullptr, nullptr, nullptr, nullptr, nullptr, nullptr, 0, N_NODES,
            nullptr, nullptr, nullptr, nullptr);
        hmma_gemm<1,1><<<dim3(NBP, S), 256, DSM>>>(
            Fhi, Flo, Whi + OFF_PRE + (size_t)i * S * CC, Wlo + OFF_PRE + (size_t)i * S * CC, CC,
            T, nullptr, nullptr, nullptr, nullptr, nullptr, pre, pre + EP, 2LL * EP, EP,
            nullptr, nullptr, nullptr, nullptr);
        hmma_gemm<1,1><<<dim3(NBP, S), 256, DSM>>>(
            Fhi, Flo, Whi + OFF_SUC + (size_t)i * S * CC, Wlo + OFF_SUC + (size_t)i * S * CC, CC,
            T, nullptr, nullptr, nullptr, nullptr, nullptr, suc, suc + EP, 2LL * EP, EP,
            nullptr, nullptr, nullptr, nullptr);
        hmma_gemm<1,1><<<NBL, 256, DSM>>>(
            Fhi, Flo, Whi + OFF_LEFT + (size_t)i * CC, Wlo + OFF_LEFT + (size_t)i * CC, 0,
            T, nullptr, nullptr, nullptr, nullptr, nullptr, left, left + EL, 0, EL,
            nullptr, nullptr, nullptr, nullptr);
        hmma_gemm<1,1><<<NBL, 256, DSM>>>(
            Fhi, Flo, Whi + OFF_RIGHT + (size_t)i * CC, Wlo + OFF_RIGHT + (size_t)i * CC, 0,
            T, nullptr, nullptr, nullptr, nullptr, nullptr, right, right + EL, 0, EL,
            nullptr, nullptr, nullptr, nullptr);
        ew_gnrelu_split<<<(N_NODES + 7) / 8, 256>>>(T, norm_g + (size_t)i * C,
                                                    norm_b + (size_t)i * C, Xhi, Xlo);
        hmma_gemm<0,2><<<NB, 256, DSM>>>(
            Xhi, Xlo, Whi + OFF_CTR2 + (size_t)i * CC, Wlo + OFF_CTR2 + (size_t)i * CC, 0,
            Fo, ctr2_g + (size_t)i * C, ctr2_b + (size_t)i * C, Fi, Fhi, Flo,
            nullptr, nullptr, 0, N_NODES,
            nullptr, nullptr, nullptr, nullptr);
    }
}